// round 1
// baseline (speedup 1.0000x reference)
#include <cuda_runtime.h>

// Problem dims
#define BRN  32768   // B*R = 16*2048
#define DN   512
#define HN   1024
#define NRELN 2048

// GEMM tiling
#define BM 128
#define BN 128
#define BK 16
#define PAD 4

// ---------------- scratch (static device globals; no allocation) ----------------
__device__ float g_attn[BRN * DN];        // 64 MB
__device__ float g_g[BRN * HN];           // 128 MB
__device__ float g_Wc[DN * DN];
__device__ float g_bc[DN];
__device__ float g_mean[BRN];
__device__ float g_rstd[BRN];
__device__ float g_maxl[2][BRN];
__device__ int   g_arg[2][BRN];
__device__ float g_sum[2][BRN];

// ---------------- W_comb = o_w @ v_w ; b_comb = o_w @ v_b + o_b ----------------
__global__ void combine_w_kernel(const float* __restrict__ o_w,
                                 const float* __restrict__ v_w,
                                 const float* __restrict__ v_b,
                                 const float* __restrict__ o_b) {
    int i  = blockIdx.x;      // output row (512 blocks)
    int tx = threadIdx.x;     // 256 threads
    __shared__ float orow[DN];
    for (int k = tx; k < DN; k += 256) orow[k] = o_w[i * DN + k];
    __syncthreads();
    float acc0 = 0.f, acc1 = 0.f;
    for (int k = 0; k < DN; k++) {
        float a = orow[k];
        acc0 = fmaf(a, v_w[k * DN + tx],       acc0);
        acc1 = fmaf(a, v_w[k * DN + tx + 256], acc1);
    }
    g_Wc[i * DN + tx]       = acc0;
    g_Wc[i * DN + tx + 256] = acc1;
    if (tx == 0) {
        float b = o_b[i];
        for (int k = 0; k < DN; k++) b = fmaf(orow[k], v_b[k], b);
        g_bc[i] = b;
    }
}

// ---------------- attn = x @ W_combT + b_comb  (NT GEMM, fp32) ----------------
__global__ __launch_bounds__(256)
void gemm_attn_kernel(const float* __restrict__ A) {
    const int K = DN, N = DN;
    __shared__ float As[BK][BM + PAD];
    __shared__ float Bs[BK][BN + PAD];
    int tx = threadIdx.x;
    int m0 = blockIdx.y * BM;
    int n0 = blockIdx.x * BN;
    int trow = (tx >> 4) * 8;
    int tcol = (tx & 15) * 8;
    float acc[8][8] = {};
    int f0 = tx * 2;

    for (int kt = 0; kt < K; kt += BK) {
#pragma unroll
        for (int q = 0; q < 2; q++) {
            int f   = f0 + q;
            int row = f >> 2;
            int c4  = (f & 3) * 4;
            float4 v = *(const float4*)&A[(size_t)(m0 + row) * K + kt + c4];
            As[c4 + 0][row] = v.x; As[c4 + 1][row] = v.y;
            As[c4 + 2][row] = v.z; As[c4 + 3][row] = v.w;
            float4 w = *(const float4*)&g_Wc[(size_t)(n0 + row) * K + kt + c4];
            Bs[c4 + 0][row] = w.x; Bs[c4 + 1][row] = w.y;
            Bs[c4 + 2][row] = w.z; Bs[c4 + 3][row] = w.w;
        }
        __syncthreads();
#pragma unroll
        for (int k = 0; k < BK; k++) {
            float a[8], b[8];
#pragma unroll
            for (int i = 0; i < 8; i++) a[i] = As[k][trow + i];
#pragma unroll
            for (int j = 0; j < 8; j++) b[j] = Bs[k][tcol + j];
#pragma unroll
            for (int i = 0; i < 8; i++)
#pragma unroll
                for (int j = 0; j < 8; j++)
                    acc[i][j] = fmaf(a[i], b[j], acc[i][j]);
        }
        __syncthreads();
    }
#pragma unroll
    for (int i = 0; i < 8; i++) {
        int r = m0 + trow + i;
#pragma unroll
        for (int j = 0; j < 8; j++)
            g_attn[(size_t)r * N + n0 + tcol + j] = acc[i][j] + g_bc[n0 + tcol + j];
    }
}

// ---------------- per-row LN stats of (attn + state) ----------------
__global__ void rowstats_kernel(const float* __restrict__ state, int sstride) {
    int r  = blockIdx.x;
    int tx = threadIdx.x;   // 128
    const float* sp = sstride ? (state + (size_t)r * DN) : state;
    float s = 0.f, s2 = 0.f;
    for (int k = tx; k < DN; k += 128) {
        float v = g_attn[(size_t)r * DN + k] + sp[k];
        s += v; s2 = fmaf(v, v, s2);
    }
    // warp reduce
    for (int o = 16; o > 0; o >>= 1) {
        s  += __shfl_xor_sync(0xffffffff, s,  o);
        s2 += __shfl_xor_sync(0xffffffff, s2, o);
    }
    __shared__ float sh[2][4];
    int w = tx >> 5;
    if ((tx & 31) == 0) { sh[0][w] = s; sh[1][w] = s2; }
    __syncthreads();
    if (tx == 0) {
        float ts = 0.f, ts2 = 0.f;
        for (int i = 0; i < 4; i++) { ts += sh[0][i]; ts2 += sh[1][i]; }
        float mean = ts * (1.f / DN);
        float var  = ts2 * (1.f / DN) - mean * mean;
        g_mean[r] = mean;
        g_rstd[r] = rsqrtf(var + 1e-5f);
    }
}

// ------- g = relu( LN(attn+state) @ w1T + b1 )  (LN fused into A-tile load) -------
__global__ __launch_bounds__(256)
void gemm_g_kernel(const float* __restrict__ state, int sstride,
                   const float* __restrict__ lng, const float* __restrict__ lnb,
                   const float* __restrict__ W1, const float* __restrict__ b1) {
    const int K = DN, N = HN;
    __shared__ float As[BK][BM + PAD];
    __shared__ float Bs[BK][BN + PAD];
    int tx = threadIdx.x;
    int m0 = blockIdx.y * BM;
    int n0 = blockIdx.x * BN;
    int trow = (tx >> 4) * 8;
    int tcol = (tx & 15) * 8;
    float acc[8][8] = {};
    int f0 = tx * 2;

    for (int kt = 0; kt < K; kt += BK) {
#pragma unroll
        for (int q = 0; q < 2; q++) {
            int f   = f0 + q;
            int row = f >> 2;
            int c4  = (f & 3) * 4;
            int gr  = m0 + row;
            float4 av = *(const float4*)&g_attn[(size_t)gr * K + kt + c4];
            const float* sp = sstride ? (state + (size_t)gr * K) : state;
            float4 sv = *(const float4*)&sp[kt + c4];
            float4 gv = *(const float4*)&lng[kt + c4];
            float4 bv = *(const float4*)&lnb[kt + c4];
            float mu = g_mean[gr], rs = g_rstd[gr];
            As[c4 + 0][row] = fmaf((av.x + sv.x - mu) * rs, gv.x, bv.x);
            As[c4 + 1][row] = fmaf((av.y + sv.y - mu) * rs, gv.y, bv.y);
            As[c4 + 2][row] = fmaf((av.z + sv.z - mu) * rs, gv.z, bv.z);
            As[c4 + 3][row] = fmaf((av.w + sv.w - mu) * rs, gv.w, bv.w);
            float4 w = *(const float4*)&W1[(size_t)(n0 + row) * K + kt + c4];
            Bs[c4 + 0][row] = w.x; Bs[c4 + 1][row] = w.y;
            Bs[c4 + 2][row] = w.z; Bs[c4 + 3][row] = w.w;
        }
        __syncthreads();
#pragma unroll
        for (int k = 0; k < BK; k++) {
            float a[8], b[8];
#pragma unroll
            for (int i = 0; i < 8; i++) a[i] = As[k][trow + i];
#pragma unroll
            for (int j = 0; j < 8; j++) b[j] = Bs[k][tcol + j];
#pragma unroll
            for (int i = 0; i < 8; i++)
#pragma unroll
                for (int j = 0; j < 8; j++)
                    acc[i][j] = fmaf(a[i], b[j], acc[i][j]);
        }
        __syncthreads();
    }
#pragma unroll
    for (int i = 0; i < 8; i++) {
        int r = m0 + trow + i;
#pragma unroll
        for (int j = 0; j < 8; j++) {
            float v = acc[i][j] + b1[n0 + tcol + j];
            g_g[(size_t)r * N + n0 + tcol + j] = v > 0.f ? v : 0.f;
        }
    }
}

// ---- logits = g @ w2T + b2, fused online (max, argmax, sumexp) row reduction ----
__global__ __launch_bounds__(256)
void logits_kernel(const float* __restrict__ W2, const float* __restrict__ b2,
                   int step) {
    const int K = HN;
    __shared__ float As[BK][BM + PAD];
    __shared__ float Bs[BK][BN + PAD];
    __shared__ float smax[BM][16];
    __shared__ float ssum[BM][16];
    __shared__ int   sarg[BM][16];
    int tx = threadIdx.x;
    int m0 = blockIdx.x * BM;
    int trow = (tx >> 4) * 8;
    int tcol = (tx & 15) * 8;
    int f0 = tx * 2;

    float rmax[8], rsum[8]; int rarg[8];
#pragma unroll
    for (int i = 0; i < 8; i++) { rmax[i] = -1e30f; rsum[i] = 0.f; rarg[i] = 0; }

    for (int n0 = 0; n0 < NRELN; n0 += BN) {
        float acc[8][8] = {};
        for (int kt = 0; kt < K; kt += BK) {
#pragma unroll
            for (int q = 0; q < 2; q++) {
                int f   = f0 + q;
                int row = f >> 2;
                int c4  = (f & 3) * 4;
                float4 v = *(const float4*)&g_g[(size_t)(m0 + row) * K + kt + c4];
                As[c4 + 0][row] = v.x; As[c4 + 1][row] = v.y;
                As[c4 + 2][row] = v.z; As[c4 + 3][row] = v.w;
                float4 w = *(const float4*)&W2[(size_t)(n0 + row) * K + kt + c4];
                Bs[c4 + 0][row] = w.x; Bs[c4 + 1][row] = w.y;
                Bs[c4 + 2][row] = w.z; Bs[c4 + 3][row] = w.w;
            }
            __syncthreads();
#pragma unroll
            for (int k = 0; k < BK; k++) {
                float a[8], b[8];
#pragma unroll
                for (int i = 0; i < 8; i++) a[i] = As[k][trow + i];
#pragma unroll
                for (int j = 0; j < 8; j++) b[j] = Bs[k][tcol + j];
#pragma unroll
                for (int i = 0; i < 8; i++)
#pragma unroll
                    for (int j = 0; j < 8; j++)
                        acc[i][j] = fmaf(a[i], b[j], acc[i][j]);
            }
            __syncthreads();
        }
        // fold this j-tile into running per-row stats (online softmax)
#pragma unroll
        for (int i = 0; i < 8; i++) {
#pragma unroll
            for (int j = 0; j < 8; j++) {
                int   jj = n0 + tcol + j;
                float l  = acc[i][j] + b2[jj];
                if (l > rmax[i]) {
                    rsum[i] = fmaf(rsum[i], __expf(rmax[i] - l), 1.f);
                    rmax[i] = l; rarg[i] = jj;
                } else {
                    rsum[i] += __expf(l - rmax[i]);
                }
            }
        }
    }

    // cross-thread (16 column groups) merge per row
    int txx = tx & 15;
#pragma unroll
    for (int i = 0; i < 8; i++) {
        smax[trow + i][txx] = rmax[i];
        ssum[trow + i][txx] = rsum[i];
        sarg[trow + i][txx] = rarg[i];
    }
    __syncthreads();
    if (tx < BM) {
        int r = tx;
        float bm = -1e30f; int ba = 0x7fffffff;
#pragma unroll
        for (int t = 0; t < 16; t++) {
            float m = smax[r][t]; int a = sarg[r][t];
            if (m > bm || (m == bm && a < ba)) { bm = m; ba = a; }
        }
        float s = 0.f;
#pragma unroll
        for (int t = 0; t < 16; t++) s = fmaf(ssum[r][t], __expf(smax[r][t] - bm), s);
        g_maxl[step][m0 + r] = bm;
        g_arg[step][m0 + r]  = ba;
        g_sum[step][m0 + r]  = s;
    }
}

// ---------------- finalize: scores / i0 / i1 / lengths ----------------
__global__ void finalize_kernel(float* __restrict__ out) {
    int r = blockIdx.x * 256 + threadIdx.x;
    if (r >= BRN) return;
    // max softmax prob = exp(max - lse) = 1 / sum(exp(l - max))
    float m0 = 1.f / g_sum[0][r];
    float m1 = 1.f / g_sum[1][r];
    int i0 = g_arg[0][r], i1 = g_arg[1][r];
    bool c0 = (i0 != 0) && (m0 >= 0.1f);
    bool c1 = c0 && (i1 != 0) && (m1 >= 0.1f);
    float score = c0 ? (c1 ? m0 * m1 : m0) : 0.f;
    int len = (int)c0 + (int)c1;
    out[r]            = score;
    out[BRN + r]      = (float)i0;
    out[2 * BRN + r]  = (float)i1;
    out[3 * BRN + r]  = (float)len;
}

// ---------------- launch ----------------
extern "C" void kernel_launch(void* const* d_in, const int* in_sizes, int n_in,
                              void* d_out, int out_size) {
    const float* x    = (const float*)d_in[0];   // [B,R,D]
    const float* na   = (const float*)d_in[1];   // [D]
    const float* v_w  = (const float*)d_in[2];
    const float* v_b  = (const float*)d_in[3];
    const float* o_w  = (const float*)d_in[4];
    const float* o_b  = (const float*)d_in[5];
    const float* ln_g = (const float*)d_in[6];
    const float* ln_b = (const float*)d_in[7];
    const float* w1   = (const float*)d_in[8];
    const float* b1   = (const float*)d_in[9];
    const float* w2   = (const float*)d_in[10];
    const float* b2   = (const float*)d_in[11];
    float* out = (float*)d_out;

    combine_w_kernel<<<DN, 256>>>(o_w, v_w, v_b, o_b);

    gemm_attn_kernel<<<dim3(DN / BN, BRN / BM), 256>>>(x);

    // step 0: state = na_emb (broadcast); step 1: state = x rows
    for (int step = 0; step < 2; step++) {
        const float* state = (step == 0) ? na : x;
        int sstride = (step == 0) ? 0 : DN;
        rowstats_kernel<<<BRN, 128>>>(state, sstride);
        gemm_g_kernel<<<dim3(HN / BN, BRN / BM), 256>>>(state, sstride,
                                                        ln_g, ln_b, w1, b1);
        logits_kernel<<<BRN / BM, 256>>>(w2, b2, step);
    }

    finalize_kernel<<<BRN / 256, 256>>>(out);
}

// round 2
// speedup vs baseline: 1.6727x; 1.6727x over previous
#include <cuda_runtime.h>

#define BRN   32768
#define DN    512
#define HN    1024
#define NRELN 2048
#define ROWS2 65536     // 2*BRN (both decode steps batched)

#define BM 128
#define BN 128
#define BK 16
#define PAD 4
#define BMP (BM + PAD)

typedef unsigned long long ull;

// ---------------- scratch (static device globals; no allocation) ----------------
__device__ float g_attn[(size_t)BRN * DN];     // 64 MB
__device__ float g_h[(size_t)ROWS2 * DN];      // 128 MB  (LN output, both steps)
__device__ float g_g[(size_t)ROWS2 * HN];      // 256 MB  (relu(h@w1T+b1), both steps)
__device__ float g_Wc[DN * DN];
__device__ float g_bc[DN];
__device__ int   g_arg[ROWS2];
__device__ float g_sum[ROWS2];

// ---------------- packed fp32x2 helpers (sm_103a FFMA2 path) ----------------
__device__ __forceinline__ ull pk2(float x) {
    ull r; asm("mov.b64 %0, {%1, %1};" : "=l"(r) : "f"(x)); return r;
}
__device__ __forceinline__ void fma2(ull& d, ull a, ull b) {
    asm("fma.rn.f32x2 %0, %1, %2, %0;" : "+l"(d) : "l"(a), "l"(b));
}
__device__ __forceinline__ float2 upk2(ull v) {
    float2 f; asm("mov.b64 {%0, %1}, %2;" : "=f"(f.x), "=f"(f.y) : "l"(v)); return f;
}

// ---------------- shared GEMM mainloop (NT layout: C = A @ B^T) ----------------
// A: [*, K] rows m0.., B: [*, K] rows n0.., both row-major, K % 16 == 0.
// 256 threads, 128x128 tile, per-thread 8x8 outputs in split 4+4 pattern.
__device__ __forceinline__ void sts_tile(float dst[BK][BMP], int rowA, int c4,
                                         float4 p0, float4 p1) {
    dst[c4 + 0][rowA] = p0.x; dst[c4 + 1][rowA] = p0.y;
    dst[c4 + 2][rowA] = p0.z; dst[c4 + 3][rowA] = p0.w;
    dst[c4 + 0][rowA + 64] = p1.x; dst[c4 + 1][rowA + 64] = p1.y;
    dst[c4 + 2][rowA + 64] = p1.z; dst[c4 + 3][rowA + 64] = p1.w;
}

__device__ __forceinline__ void gemm_mainloop(
    const float* __restrict__ A, const float* __restrict__ B, int K,
    float As[2][BK][BMP], float Bs[2][BK][BMP],
    ull acc[8][4], int tx, int ra, int cb)
{
    const int NT = K / BK;
    const int rowA = tx >> 2;          // 0..63 (q=0); +64 for q=1
    const int c4   = (tx & 3) * 4;
    const float* pA0 = A + (size_t)rowA * K + c4;
    const float* pA1 = A + (size_t)(rowA + 64) * K + c4;
    const float* pB0 = B + (size_t)rowA * K + c4;
    const float* pB1 = B + (size_t)(rowA + 64) * K + c4;

    // prologue: tile 0 -> buf 0
    float4 a0 = *(const float4*)pA0;
    float4 a1 = *(const float4*)pA1;
    float4 b0 = *(const float4*)pB0;
    float4 b1 = *(const float4*)pB1;
    sts_tile(As[0], rowA, c4, a0, a1);
    sts_tile(Bs[0], rowA, c4, b0, b1);

    for (int t = 0; t < NT; t++) {
        int cur = t & 1;
        bool more = (t + 1 < NT);
        __syncthreads();             // buf[cur] fully stored; prior reads done
        if (more) {
            int off = (t + 1) * BK;
            a0 = *(const float4*)(pA0 + off);
            a1 = *(const float4*)(pA1 + off);
            b0 = *(const float4*)(pB0 + off);
            b1 = *(const float4*)(pB1 + off);
        }
#pragma unroll
        for (int k = 0; k < BK; k++) {
            float4 fa0 = *(const float4*)&As[cur][k][ra];
            float4 fa1 = *(const float4*)&As[cur][k][ra + 64];
            ulonglong2 fb0 = *(const ulonglong2*)&Bs[cur][k][cb];
            ulonglong2 fb1 = *(const ulonglong2*)&Bs[cur][k][cb + 64];
            float av[8] = {fa0.x, fa0.y, fa0.z, fa0.w,
                           fa1.x, fa1.y, fa1.z, fa1.w};
#pragma unroll
            for (int i = 0; i < 8; i++) {
                ull ap = pk2(av[i]);
                fma2(acc[i][0], ap, fb0.x);
                fma2(acc[i][1], ap, fb0.y);
                fma2(acc[i][2], ap, fb1.x);
                fma2(acc[i][3], ap, fb1.y);
            }
        }
        if (more) {
            sts_tile(As[cur ^ 1], rowA, c4, a0, a1);
            sts_tile(Bs[cur ^ 1], rowA, c4, b0, b1);
        }
    }
}

__device__ __forceinline__ int ri_of(int ra, int i) { return ra + (i < 4 ? i : 60 + i); }
__device__ __forceinline__ int cj_of(int cb, int j) { return cb + (j < 2 ? 2 * j : 60 + 2 * j); }

// ---------------- W_comb = o_w @ v_w ; b_comb = o_w @ v_b + o_b ----------------
__global__ void combine_w_kernel(const float* __restrict__ o_w,
                                 const float* __restrict__ v_w,
                                 const float* __restrict__ v_b,
                                 const float* __restrict__ o_b) {
    int i  = blockIdx.x;
    int tx = threadIdx.x;
    __shared__ float orow[DN];
    for (int k = tx; k < DN; k += 256) orow[k] = o_w[i * DN + k];
    __syncthreads();
    float acc0 = 0.f, acc1 = 0.f;
    for (int k = 0; k < DN; k++) {
        float a = orow[k];
        acc0 = fmaf(a, v_w[k * DN + tx],       acc0);
        acc1 = fmaf(a, v_w[k * DN + tx + 256], acc1);
    }
    g_Wc[i * DN + tx]       = acc0;
    g_Wc[i * DN + tx + 256] = acc1;
    if (tx == 0) {
        float b = o_b[i];
        for (int k = 0; k < DN; k++) b = fmaf(orow[k], v_b[k], b);
        g_bc[i] = b;
    }
}

// ---------------- attn = x @ W_combT + b_comb ----------------
__global__ __launch_bounds__(256, 2)
void gemm_attn_kernel(const float* __restrict__ x) {
    __shared__ __align__(16) float As[2][BK][BMP];
    __shared__ __align__(16) float Bs[2][BK][BMP];
    int tx = threadIdx.x;
    int m0 = blockIdx.y * BM, n0 = blockIdx.x * BN;
    int ra = (tx >> 4) * 4, cb = (tx & 15) * 4;
    ull acc[8][4];
#pragma unroll
    for (int i = 0; i < 8; i++)
#pragma unroll
        for (int j = 0; j < 4; j++) acc[i][j] = 0ull;

    gemm_mainloop(x + (size_t)m0 * DN, g_Wc + (size_t)n0 * DN, DN, As, Bs, acc, tx, ra, cb);

#pragma unroll
    for (int i = 0; i < 8; i++) {
        int r = m0 + ri_of(ra, i);
#pragma unroll
        for (int j = 0; j < 4; j++) {
            int c = n0 + cj_of(cb, j);
            float2 v = upk2(acc[i][j]);
            v.x += g_bc[c]; v.y += g_bc[c + 1];
            *(float2*)&g_attn[(size_t)r * DN + c] = v;
        }
    }
}

// ---------------- h = LN(attn + state), both steps batched ----------------
__global__ __launch_bounds__(128)
void ln_apply_kernel(const float* __restrict__ x, const float* __restrict__ na,
                     const float* __restrict__ lng, const float* __restrict__ lnb) {
    int rr = blockIdx.x;                 // 0..65535
    int tx = threadIdx.x;                // 128 threads, 4 floats each
    int r  = rr & (BRN - 1);
    const float* sp = (rr < BRN) ? (na + tx * 4) : (x + (size_t)r * DN + tx * 4);
    float4 a = *(const float4*)&g_attn[(size_t)r * DN + tx * 4];
    float4 s = *(const float4*)sp;
    float vx = a.x + s.x, vy = a.y + s.y, vz = a.z + s.z, vw = a.w + s.w;
    float sum = vx + vy + vz + vw;
    float sq  = vx * vx + vy * vy + vz * vz + vw * vw;
#pragma unroll
    for (int o = 16; o > 0; o >>= 1) {
        sum += __shfl_xor_sync(0xffffffff, sum, o);
        sq  += __shfl_xor_sync(0xffffffff, sq,  o);
    }
    __shared__ float sh[8];
    int w = tx >> 5;
    if ((tx & 31) == 0) { sh[w] = sum; sh[4 + w] = sq; }
    __syncthreads();
    float ts  = sh[0] + sh[1] + sh[2] + sh[3];
    float ts2 = sh[4] + sh[5] + sh[6] + sh[7];
    float mean = ts * (1.f / DN);
    float rstd = rsqrtf(ts2 * (1.f / DN) - mean * mean + 1e-5f);
    float4 g = *(const float4*)&lng[tx * 4];
    float4 b = *(const float4*)&lnb[tx * 4];
    float4 o;
    o.x = fmaf((vx - mean) * rstd, g.x, b.x);
    o.y = fmaf((vy - mean) * rstd, g.y, b.y);
    o.z = fmaf((vz - mean) * rstd, g.z, b.z);
    o.w = fmaf((vw - mean) * rstd, g.w, b.w);
    *(float4*)&g_h[(size_t)rr * DN + tx * 4] = o;
}

// ---------------- g = relu(h @ w1T + b1), both steps ----------------
__global__ __launch_bounds__(256, 2)
void gemm_g_kernel(const float* __restrict__ W1, const float* __restrict__ b1) {
    __shared__ __align__(16) float As[2][BK][BMP];
    __shared__ __align__(16) float Bs[2][BK][BMP];
    int tx = threadIdx.x;
    int m0 = blockIdx.y * BM, n0 = blockIdx.x * BN;
    int ra = (tx >> 4) * 4, cb = (tx & 15) * 4;
    ull acc[8][4];
#pragma unroll
    for (int i = 0; i < 8; i++)
#pragma unroll
        for (int j = 0; j < 4; j++) acc[i][j] = 0ull;

    gemm_mainloop(g_h + (size_t)m0 * DN, W1 + (size_t)n0 * DN, DN, As, Bs, acc, tx, ra, cb);

#pragma unroll
    for (int i = 0; i < 8; i++) {
        int r = m0 + ri_of(ra, i);
#pragma unroll
        for (int j = 0; j < 4; j++) {
            int c = n0 + cj_of(cb, j);
            float2 v = upk2(acc[i][j]);
            v.x += b1[c];     v.y += b1[c + 1];
            v.x = v.x > 0.f ? v.x : 0.f;
            v.y = v.y > 0.f ? v.y : 0.f;
            *(float2*)&g_g[(size_t)r * HN + c] = v;
        }
    }
}

// ---- logits = g @ w2T + b2, fused online (max, argmax, sumexp) ----
__global__ __launch_bounds__(256, 2)
void logits_kernel(const float* __restrict__ W2, const float* __restrict__ b2) {
    __shared__ __align__(16) float As[2][BK][BMP];
    __shared__ __align__(16) float Bs[2][BK][BMP];
    int tx = threadIdx.x;
    int m0 = blockIdx.x * BM;
    int ra = (tx >> 4) * 4, cb = (tx & 15) * 4;

    float rmax[8], rsum[8]; int rarg[8];
#pragma unroll
    for (int i = 0; i < 8; i++) { rmax[i] = -1e30f; rsum[i] = 0.f; rarg[i] = 0; }

    for (int n0 = 0; n0 < NRELN; n0 += BN) {
        ull acc[8][4];
#pragma unroll
        for (int i = 0; i < 8; i++)
#pragma unroll
            for (int j = 0; j < 4; j++) acc[i][j] = 0ull;

        gemm_mainloop(g_g + (size_t)m0 * HN, W2 + (size_t)n0 * HN, HN, As, Bs, acc, tx, ra, cb);

#pragma unroll
        for (int i = 0; i < 8; i++) {
#pragma unroll
            for (int j = 0; j < 4; j++) {
                int c = n0 + cj_of(cb, j);
                float2 v = upk2(acc[i][j]);
                float l0 = v.x + b2[c];
                float l1 = v.y + b2[c + 1];
                if (l0 > rmax[i]) {
                    rsum[i] = fmaf(rsum[i], __expf(rmax[i] - l0), 1.f);
                    rmax[i] = l0; rarg[i] = c;
                } else rsum[i] += __expf(l0 - rmax[i]);
                if (l1 > rmax[i]) {
                    rsum[i] = fmaf(rsum[i], __expf(rmax[i] - l1), 1.f);
                    rmax[i] = l1; rarg[i] = c + 1;
                } else rsum[i] += __expf(l1 - rmax[i]);
            }
        }
        __syncthreads();   // done with smem buffers before next mainloop prologue STS
    }

    // cross-thread merge: 16 threads (same tx>>4) own each row
    float* smax = &As[0][0][0];          // 2048 floats
    float* ssum = smax + 2048;           // fits: As = 4224 floats
    int*   sarg = (int*)&Bs[0][0][0];
    int txx = tx & 15;
#pragma unroll
    for (int i = 0; i < 8; i++) {
        int row = ri_of(ra, i);
        smax[row * 16 + txx] = rmax[i];
        ssum[row * 16 + txx] = rsum[i];
        sarg[row * 16 + txx] = rarg[i];
    }
    __syncthreads();
    if (tx < BM) {
        int row = tx;
        float bm = -1e30f; int ba = 0x7fffffff;
#pragma unroll
        for (int t = 0; t < 16; t++) {
            float m = smax[row * 16 + t]; int a = sarg[row * 16 + t];
            if (m > bm || (m == bm && a < ba)) { bm = m; ba = a; }
        }
        float s = 0.f;
#pragma unroll
        for (int t = 0; t < 16; t++)
            s = fmaf(ssum[row * 16 + t], __expf(smax[row * 16 + t] - bm), s);
        int rr = m0 + row;
        g_arg[rr] = ba;
        g_sum[rr] = s;
    }
}

// ---------------- finalize: scores / i0 / i1 / lengths ----------------
__global__ void finalize_kernel(float* __restrict__ out) {
    int r = blockIdx.x * 256 + threadIdx.x;
    if (r >= BRN) return;
    float m0 = 1.f / g_sum[r];
    float m1 = 1.f / g_sum[BRN + r];
    int i0 = g_arg[r], i1 = g_arg[BRN + r];
    bool c0 = (i0 != 0) && (m0 >= 0.1f);
    bool c1 = c0 && (i1 != 0) && (m1 >= 0.1f);
    float score = c0 ? (c1 ? m0 * m1 : m0) : 0.f;
    int len = (int)c0 + (int)c1;
    out[r]           = score;
    out[BRN + r]     = (float)i0;
    out[2 * BRN + r] = (float)i1;
    out[3 * BRN + r] = (float)len;
}

// ---------------- launch ----------------
extern "C" void kernel_launch(void* const* d_in, const int* in_sizes, int n_in,
                              void* d_out, int out_size) {
    const float* x    = (const float*)d_in[0];
    const float* na   = (const float*)d_in[1];
    const float* v_w  = (const float*)d_in[2];
    const float* v_b  = (const float*)d_in[3];
    const float* o_w  = (const float*)d_in[4];
    const float* o_b  = (const float*)d_in[5];
    const float* ln_g = (const float*)d_in[6];
    const float* ln_b = (const float*)d_in[7];
    const float* w1   = (const float*)d_in[8];
    const float* b1   = (const float*)d_in[9];
    const float* w2   = (const float*)d_in[10];
    const float* b2   = (const float*)d_in[11];
    float* out = (float*)d_out;

    combine_w_kernel<<<DN, 256>>>(o_w, v_w, v_b, o_b);
    gemm_attn_kernel<<<dim3(DN / BN, BRN / BM), 256>>>(x);
    ln_apply_kernel<<<ROWS2, 128>>>(x, na, ln_g, ln_b);
    gemm_g_kernel<<<dim3(HN / BN, ROWS2 / BM), 256>>>(w1, b1);
    logits_kernel<<<ROWS2 / BM, 256>>>(w2, b2);
    finalize_kernel<<<BRN / 256, 256>>>(out);
}

// round 3
// speedup vs baseline: 1.6741x; 1.0009x over previous
#include <cuda_runtime.h>

#define BRN   32768
#define DN    512
#define HN    1024
#define NRELN 2048
#define ROWS2 65536     // 2*BRN (both decode steps batched)

#define BM 128
#define BN 128
#define BK 16
#define PAD 4
#define BMP (BM + PAD)

typedef unsigned long long ull;

// ---------------- scratch (static device globals; no allocation) ----------------
__device__ float g_attn[(size_t)BRN * DN];     // 64 MB
__device__ float g_h[(size_t)ROWS2 * DN];      // 128 MB  (LN output, both steps)
__device__ float g_g[(size_t)ROWS2 * HN];      // 256 MB  (relu(h@w1T+b1), both steps)
__device__ float g_Wc[DN * DN];
__device__ float g_bc[DN];
__device__ int   g_arg[ROWS2];
__device__ float g_sum[ROWS2];

// ---------------- packed fp32x2 helpers (sm_103a FFMA2 path) ----------------
__device__ __forceinline__ ull pk2(float x) {
    ull r; asm("mov.b64 %0, {%1, %1};" : "=l"(r) : "f"(x)); return r;
}
__device__ __forceinline__ void fma2(ull& d, ull a, ull b) {
    asm("fma.rn.f32x2 %0, %1, %2, %0;" : "+l"(d) : "l"(a), "l"(b));
}
__device__ __forceinline__ float2 upk2(ull v) {
    float2 f; asm("mov.b64 {%0, %1}, %2;" : "=f"(f.x), "=f"(f.y) : "l"(v)); return f;
}

// ---------------- shared GEMM mainloop (NT layout: C = A @ B^T) ----------------
// A: [*, K] rows m0.., B: [*, K] rows n0.., both row-major, K % 16 == 0.
// 256 threads, 128x128 tile, per-thread 8x8 outputs in split 4+4 pattern.
__device__ __forceinline__ void sts_tile(float dst[BK][BMP], int rowA, int c4,
                                         float4 p0, float4 p1) {
    dst[c4 + 0][rowA] = p0.x; dst[c4 + 1][rowA] = p0.y;
    dst[c4 + 2][rowA] = p0.z; dst[c4 + 3][rowA] = p0.w;
    dst[c4 + 0][rowA + 64] = p1.x; dst[c4 + 1][rowA + 64] = p1.y;
    dst[c4 + 2][rowA + 64] = p1.z; dst[c4 + 3][rowA + 64] = p1.w;
}

__device__ __forceinline__ void gemm_mainloop(
    const float* __restrict__ A, const float* __restrict__ B, int K,
    float As[2][BK][BMP], float Bs[2][BK][BMP],
    ull acc[8][4], int tx, int ra, int cb)
{
    const int NT = K / BK;
    const int rowA = tx >> 2;          // 0..63 (q=0); +64 for q=1
    const int c4   = (tx & 3) * 4;
    const float* pA0 = A + (size_t)rowA * K + c4;
    const float* pA1 = A + (size_t)(rowA + 64) * K + c4;
    const float* pB0 = B + (size_t)rowA * K + c4;
    const float* pB1 = B + (size_t)(rowA + 64) * K + c4;

    // prologue: tile 0 -> buf 0
    float4 a0 = *(const float4*)pA0;
    float4 a1 = *(const float4*)pA1;
    float4 b0 = *(const float4*)pB0;
    float4 b1 = *(const float4*)pB1;
    sts_tile(As[0], rowA, c4, a0, a1);
    sts_tile(Bs[0], rowA, c4, b0, b1);

    for (int t = 0; t < NT; t++) {
        int cur = t & 1;
        bool more = (t + 1 < NT);
        __syncthreads();             // buf[cur] fully stored; prior reads done
        if (more) {
            int off = (t + 1) * BK;
            a0 = *(const float4*)(pA0 + off);
            a1 = *(const float4*)(pA1 + off);
            b0 = *(const float4*)(pB0 + off);
            b1 = *(const float4*)(pB1 + off);
        }
#pragma unroll
        for (int k = 0; k < BK; k++) {
            float4 fa0 = *(const float4*)&As[cur][k][ra];
            float4 fa1 = *(const float4*)&As[cur][k][ra + 64];
            ulonglong2 fb0 = *(const ulonglong2*)&Bs[cur][k][cb];
            ulonglong2 fb1 = *(const ulonglong2*)&Bs[cur][k][cb + 64];
            float av[8] = {fa0.x, fa0.y, fa0.z, fa0.w,
                           fa1.x, fa1.y, fa1.z, fa1.w};
#pragma unroll
            for (int i = 0; i < 8; i++) {
                ull ap = pk2(av[i]);
                fma2(acc[i][0], ap, fb0.x);
                fma2(acc[i][1], ap, fb0.y);
                fma2(acc[i][2], ap, fb1.x);
                fma2(acc[i][3], ap, fb1.y);
            }
        }
        if (more) {
            sts_tile(As[cur ^ 1], rowA, c4, a0, a1);
            sts_tile(Bs[cur ^ 1], rowA, c4, b0, b1);
        }
    }
}

__device__ __forceinline__ int ri_of(int ra, int i) { return ra + (i < 4 ? i : 60 + i); }
__device__ __forceinline__ int cj_of(int cb, int j) { return cb + (j < 2 ? 2 * j : 60 + 2 * j); }

// ---------------- W_comb = o_w @ v_w ; b_comb = o_w @ v_b + o_b ----------------
__global__ void combine_w_kernel(const float* __restrict__ o_w,
                                 const float* __restrict__ v_w,
                                 const float* __restrict__ v_b,
                                 const float* __restrict__ o_b) {
    int i  = blockIdx.x;
    int tx = threadIdx.x;
    __shared__ float orow[DN];
    for (int k = tx; k < DN; k += 256) orow[k] = o_w[i * DN + k];
    __syncthreads();
    float acc0 = 0.f, acc1 = 0.f;
    for (int k = 0; k < DN; k++) {
        float a = orow[k];
        acc0 = fmaf(a, v_w[k * DN + tx],       acc0);
        acc1 = fmaf(a, v_w[k * DN + tx + 256], acc1);
    }
    g_Wc[i * DN + tx]       = acc0;
    g_Wc[i * DN + tx + 256] = acc1;
    if (tx == 0) {
        float b = o_b[i];
        for (int k = 0; k < DN; k++) b = fmaf(orow[k], v_b[k], b);
        g_bc[i] = b;
    }
}

// ---------------- attn = x @ W_combT + b_comb ----------------
__global__ __launch_bounds__(256, 2)
void gemm_attn_kernel(const float* __restrict__ x) {
    __shared__ __align__(16) float As[2][BK][BMP];
    __shared__ __align__(16) float Bs[2][BK][BMP];
    int tx = threadIdx.x;
    int m0 = blockIdx.y * BM, n0 = blockIdx.x * BN;
    int ra = (tx >> 4) * 4, cb = (tx & 15) * 4;
    ull acc[8][4];
#pragma unroll
    for (int i = 0; i < 8; i++)
#pragma unroll
        for (int j = 0; j < 4; j++) acc[i][j] = 0ull;

    gemm_mainloop(x + (size_t)m0 * DN, g_Wc + (size_t)n0 * DN, DN, As, Bs, acc, tx, ra, cb);

#pragma unroll
    for (int i = 0; i < 8; i++) {
        int r = m0 + ri_of(ra, i);
#pragma unroll
        for (int j = 0; j < 4; j++) {
            int c = n0 + cj_of(cb, j);
            float2 v = upk2(acc[i][j]);
            v.x += g_bc[c]; v.y += g_bc[c + 1];
            *(float2*)&g_attn[(size_t)r * DN + c] = v;
        }
    }
}

// ---------------- h = LN(attn + state), both steps batched ----------------
__global__ __launch_bounds__(128)
void ln_apply_kernel(const float* __restrict__ x, const float* __restrict__ na,
                     const float* __restrict__ lng, const float* __restrict__ lnb) {
    int rr = blockIdx.x;                 // 0..65535
    int tx = threadIdx.x;                // 128 threads, 4 floats each
    int r  = rr & (BRN - 1);
    const float* sp = (rr < BRN) ? (na + tx * 4) : (x + (size_t)r * DN + tx * 4);
    float4 a = *(const float4*)&g_attn[(size_t)r * DN + tx * 4];
    float4 s = *(const float4*)sp;
    float vx = a.x + s.x, vy = a.y + s.y, vz = a.z + s.z, vw = a.w + s.w;
    float sum = vx + vy + vz + vw;
    float sq  = vx * vx + vy * vy + vz * vz + vw * vw;
#pragma unroll
    for (int o = 16; o > 0; o >>= 1) {
        sum += __shfl_xor_sync(0xffffffff, sum, o);
        sq  += __shfl_xor_sync(0xffffffff, sq,  o);
    }
    __shared__ float sh[8];
    int w = tx >> 5;
    if ((tx & 31) == 0) { sh[w] = sum; sh[4 + w] = sq; }
    __syncthreads();
    float ts  = sh[0] + sh[1] + sh[2] + sh[3];
    float ts2 = sh[4] + sh[5] + sh[6] + sh[7];
    float mean = ts * (1.f / DN);
    float rstd = rsqrtf(ts2 * (1.f / DN) - mean * mean + 1e-5f);
    float4 g = *(const float4*)&lng[tx * 4];
    float4 b = *(const float4*)&lnb[tx * 4];
    float4 o;
    o.x = fmaf((vx - mean) * rstd, g.x, b.x);
    o.y = fmaf((vy - mean) * rstd, g.y, b.y);
    o.z = fmaf((vz - mean) * rstd, g.z, b.z);
    o.w = fmaf((vw - mean) * rstd, g.w, b.w);
    *(float4*)&g_h[(size_t)rr * DN + tx * 4] = o;
}

// ---------------- g = relu(h @ w1T + b1), both steps ----------------
__global__ __launch_bounds__(256, 2)
void gemm_g_kernel(const float* __restrict__ W1, const float* __restrict__ b1) {
    __shared__ __align__(16) float As[2][BK][BMP];
    __shared__ __align__(16) float Bs[2][BK][BMP];
    int tx = threadIdx.x;
    int m0 = blockIdx.y * BM, n0 = blockIdx.x * BN;
    int ra = (tx >> 4) * 4, cb = (tx & 15) * 4;
    ull acc[8][4];
#pragma unroll
    for (int i = 0; i < 8; i++)
#pragma unroll
        for (int j = 0; j < 4; j++) acc[i][j] = 0ull;

    gemm_mainloop(g_h + (size_t)m0 * DN, W1 + (size_t)n0 * DN, DN, As, Bs, acc, tx, ra, cb);

#pragma unroll
    for (int i = 0; i < 8; i++) {
        int r = m0 + ri_of(ra, i);
#pragma unroll
        for (int j = 0; j < 4; j++) {
            int c = n0 + cj_of(cb, j);
            float2 v = upk2(acc[i][j]);
            v.x += b1[c];     v.y += b1[c + 1];
            v.x = v.x > 0.f ? v.x : 0.f;
            v.y = v.y > 0.f ? v.y : 0.f;
            *(float2*)&g_g[(size_t)r * HN + c] = v;
        }
    }
}

// ---- logits = g @ w2T + b2, fused online (max, argmax, sumexp) ----
__global__ __launch_bounds__(256, 2)
void logits_kernel(const float* __restrict__ W2, const float* __restrict__ b2) {
    __shared__ __align__(16) float As[2][BK][BMP];
    __shared__ __align__(16) float Bs[2][BK][BMP];
    int tx = threadIdx.x;
    int m0 = blockIdx.x * BM;
    int ra = (tx >> 4) * 4, cb = (tx & 15) * 4;

    float rmax[8], rsum[8]; int rarg[8];
#pragma unroll
    for (int i = 0; i < 8; i++) { rmax[i] = -1e30f; rsum[i] = 0.f; rarg[i] = 0; }

    for (int n0 = 0; n0 < NRELN; n0 += BN) {
        ull acc[8][4];
#pragma unroll
        for (int i = 0; i < 8; i++)
#pragma unroll
            for (int j = 0; j < 4; j++) acc[i][j] = 0ull;

        gemm_mainloop(g_g + (size_t)m0 * HN, W2 + (size_t)n0 * HN, HN, As, Bs, acc, tx, ra, cb);

#pragma unroll
        for (int i = 0; i < 8; i++) {
#pragma unroll
            for (int j = 0; j < 4; j++) {
                int c = n0 + cj_of(cb, j);
                float2 v = upk2(acc[i][j]);
                float l0 = v.x + b2[c];
                float l1 = v.y + b2[c + 1];
                if (l0 > rmax[i]) {
                    rsum[i] = fmaf(rsum[i], __expf(rmax[i] - l0), 1.f);
                    rmax[i] = l0; rarg[i] = c;
                } else rsum[i] += __expf(l0 - rmax[i]);
                if (l1 > rmax[i]) {
                    rsum[i] = fmaf(rsum[i], __expf(rmax[i] - l1), 1.f);
                    rmax[i] = l1; rarg[i] = c + 1;
                } else rsum[i] += __expf(l1 - rmax[i]);
            }
        }
        __syncthreads();   // done with smem buffers before next mainloop prologue STS
    }

    // cross-thread merge: 16 threads (same tx>>4) own each row
    float* smax = &As[0][0][0];          // 2048 floats
    float* ssum = smax + 2048;           // fits: As = 4224 floats
    int*   sarg = (int*)&Bs[0][0][0];
    int txx = tx & 15;
#pragma unroll
    for (int i = 0; i < 8; i++) {
        int row = ri_of(ra, i);
        smax[row * 16 + txx] = rmax[i];
        ssum[row * 16 + txx] = rsum[i];
        sarg[row * 16 + txx] = rarg[i];
    }
    __syncthreads();
    if (tx < BM) {
        int row = tx;
        float bm = -1e30f; int ba = 0x7fffffff;
#pragma unroll
        for (int t = 0; t < 16; t++) {
            float m = smax[row * 16 + t]; int a = sarg[row * 16 + t];
            if (m > bm || (m == bm && a < ba)) { bm = m; ba = a; }
        }
        float s = 0.f;
#pragma unroll
        for (int t = 0; t < 16; t++)
            s = fmaf(ssum[row * 16 + t], __expf(smax[row * 16 + t] - bm), s);
        int rr = m0 + row;
        g_arg[rr] = ba;
        g_sum[rr] = s;
    }
}

// ---------------- finalize: scores / i0 / i1 / lengths ----------------
__global__ void finalize_kernel(float* __restrict__ out) {
    int r = blockIdx.x * 256 + threadIdx.x;
    if (r >= BRN) return;
    float m0 = 1.f / g_sum[r];
    float m1 = 1.f / g_sum[BRN + r];
    int i0 = g_arg[r], i1 = g_arg[BRN + r];
    bool c0 = (i0 != 0) && (m0 >= 0.1f);
    bool c1 = c0 && (i1 != 0) && (m1 >= 0.1f);
    float score = c0 ? (c1 ? m0 * m1 : m0) : 0.f;
    int len = (int)c0 + (int)c1;
    out[r]           = score;
    out[BRN + r]     = (float)i0;
    out[2 * BRN + r] = (float)i1;
    out[3 * BRN + r] = (float)len;
}

// ---------------- launch ----------------
extern "C" void kernel_launch(void* const* d_in, const int* in_sizes, int n_in,
                              void* d_out, int out_size) {
    const float* x    = (const float*)d_in[0];
    const float* na   = (const float*)d_in[1];
    const float* v_w  = (const float*)d_in[2];
    const float* v_b  = (const float*)d_in[3];
    const float* o_w  = (const float*)d_in[4];
    const float* o_b  = (const float*)d_in[5];
    const float* ln_g = (const float*)d_in[6];
    const float* ln_b = (const float*)d_in[7];
    const float* w1   = (const float*)d_in[8];
    const float* b1   = (const float*)d_in[9];
    const float* w2   = (const float*)d_in[10];
    const float* b2   = (const float*)d_in[11];
    float* out = (float*)d_out;

    combine_w_kernel<<<DN, 256>>>(o_w, v_w, v_b, o_b);
    gemm_attn_kernel<<<dim3(DN / BN, BRN / BM), 256>>>(x);
    ln_apply_kernel<<<ROWS2, 128>>>(x, na, ln_g, ln_b);
    gemm_g_kernel<<<dim3(HN / BN, ROWS2 / BM), 256>>>(w1, b1);
    logits_kernel<<<ROWS2 / BM, 256>>>(w2, b2);
    finalize_kernel<<<BRN / 256, 256>>>(out);
}

// round 6
// speedup vs baseline: 3.0611x; 1.8285x over previous
#include <cuda_runtime.h>
#include <cuda_fp16.h>
#include <cstdint>

#define BRN 32768
#define DN 512
#define HN 1024
#define NRELN 2048
#define ROWS2 65536
#define BK 16
#define BMP 132
typedef unsigned long long ull;

__device__ float g_attn[(size_t)BRN * DN];
__device__ float g_Wc[DN * DN];
__device__ float g_bc[DN];
__device__ uint8_t g_himg[(size_t)(ROWS2/128)*(DN/16)*8192];
__device__ uint8_t g_gimg[(size_t)(ROWS2/128)*(HN/16)*8192];
__device__ uint8_t g_w1img[(size_t)(HN/128)*(DN/16)*8192];
__device__ uint8_t g_w2img[(size_t)(NRELN/128)*(HN/16)*8192];
__device__ float g_sum[ROWS2];
__device__ int   g_arg[ROWS2];

__device__ __forceinline__ ull pk2(float x){ ull r; asm("mov.b64 %0, {%1, %1};" : "=l"(r) : "f"(x)); return r; }
__device__ __forceinline__ void fma2(ull& d, ull a, ull b){ asm("fma.rn.f32x2 %0, %1, %2, %0;" : "+l"(d) : "l"(a), "l"(b)); }
__device__ __forceinline__ float2 upk2(ull v){ float2 f; asm("mov.b64 {%0, %1}, %2;" : "=f"(f.x), "=f"(f.y) : "l"(v)); return f; }
__device__ __forceinline__ uint32_t smem_u32(const void* p){
    uint32_t a; asm("{ .reg .u64 t; cvta.to.shared.u64 t, %1; cvt.u32.u64 %0, t; }" : "=r"(a) : "l"(p)); return a;
}
__device__ __forceinline__ void cpa16(uint32_t d, const void* s){
    asm volatile("cp.async.cg.shared.global [%0],[%1],16;" :: "r"(d), "l"(s));
}
__device__ __forceinline__ void hmma(float* c, const uint32_t* a, uint32_t b0, uint32_t b1){
    asm volatile("mma.sync.aligned.m16n8k16.row.col.f32.f16.f16.f32 {%0,%1,%2,%3},{%4,%5,%6,%7},{%8,%9},{%0,%1,%2,%3};"
        : "+f"(c[0]), "+f"(c[1]), "+f"(c[2]), "+f"(c[3])
        : "r"(a[0]), "r"(a[1]), "r"(a[2]), "r"(a[3]), "r"(b0), "r"(b1));
}
__device__ __forceinline__ float fexp(float x){
    x = fmaxf(x, -80.f);
    return __uint_as_float((uint32_t)(int)(fmaf(x, 12102203.0f, 1064866805.0f)));
}
__device__ __forceinline__ void hsplit2(float x, float y, uint32_t& hi, uint32_t& lo){
    __half hx = __float2half_rn(x), hy = __float2half_rn(y);
    __half lx = __float2half_rn(x - __half2float(hx)), ly = __float2half_rn(y - __half2float(hy));
    hi = (uint32_t)__half_as_ushort(hx) | ((uint32_t)__half_as_ushort(hy) << 16);
    lo = (uint32_t)__half_as_ushort(lx) | ((uint32_t)__half_as_ushort(ly) << 16);
}
// fragment-image byte offsets (A: rows x k, B: n x k), tile = 128x16, 2 planes, 8KB
__device__ __forceinline__ size_t aoff(int row, int k, int plane, int KT){
    int mblk = row >> 7, mi = (row >> 4) & 7, g = row & 7, rb = (row >> 3) & 1;
    int kt = k >> 4, tg = (k >> 1) & 3, kb = (k >> 3) & 1;
    return (size_t)(mblk * KT + kt) * 8192 + (size_t)((((plane*8 + mi)*32 + g*4 + tg)*4 + rb + 2*kb) * 4);
}
__device__ __forceinline__ size_t boff(int n, int k, int plane, int KT){
    int nblk = n >> 7, nj = (n >> 3) & 15, g = n & 7;
    int kt = k >> 4, tg = (k >> 1) & 3, kb = (k >> 3) & 1;
    return (size_t)(nblk * KT + kt) * 8192 + (size_t)(((((nj*32 + g*4 + tg)*2 + plane)*2 + kb)) * 4);
}

// ============ combine W ============
__global__ void combine_w_kernel(const float* __restrict__ o_w, const float* __restrict__ v_w,
                                 const float* __restrict__ v_b, const float* __restrict__ o_b){
    int i = blockIdx.x, tx = threadIdx.x;
    __shared__ float orow[DN];
    for (int k = tx; k < DN; k += 256) orow[k] = o_w[i*DN + k];
    __syncthreads();
    float a0 = 0.f, a1 = 0.f;
    for (int k = 0; k < DN; k++){ float a = orow[k];
        a0 = fmaf(a, v_w[k*DN + tx], a0); a1 = fmaf(a, v_w[k*DN + tx + 256], a1); }
    g_Wc[i*DN + tx] = a0; g_Wc[i*DN + tx + 256] = a1;
    if (tx == 0){ float b = o_b[i];
        for (int k = 0; k < DN; k++) b = fmaf(orow[k], v_b[k], b);
        g_bc[i] = b; }
}

// ============ attn = x @ WcT + bc (exact fp32, FFMA2) ============
__device__ __forceinline__ void sts_tile(float dst[BK][BMP], int rowA, int c4, float4 p0, float4 p1){
    dst[c4+0][rowA] = p0.x; dst[c4+1][rowA] = p0.y; dst[c4+2][rowA] = p0.z; dst[c4+3][rowA] = p0.w;
    dst[c4+0][rowA+64] = p1.x; dst[c4+1][rowA+64] = p1.y; dst[c4+2][rowA+64] = p1.z; dst[c4+3][rowA+64] = p1.w;
}
__device__ __forceinline__ int ri_of(int ra, int i){ return ra + (i < 4 ? i : 60 + i); }
__device__ __forceinline__ int cj_of(int cb, int j){ return cb + (j < 2 ? 2*j : 60 + 2*j); }

__global__ __launch_bounds__(256, 2)
void gemm_attn_kernel(const float* __restrict__ x){
    __shared__ __align__(16) float As[2][BK][BMP];
    __shared__ __align__(16) float Bs[2][BK][BMP];
    int tx = threadIdx.x, m0 = blockIdx.y*128, n0 = blockIdx.x*128;
    int ra = (tx >> 4)*4, cb = (tx & 15)*4;
    ull acc[8][4];
#pragma unroll
    for (int i = 0; i < 8; i++)
#pragma unroll
        for (int j = 0; j < 4; j++) acc[i][j] = 0ull;
    const int K = DN, NT = K/BK;
    const int rowA = tx >> 2, c4 = (tx & 3)*4;
    const float* pA0 = x + (size_t)(m0+rowA)*K + c4;
    const float* pA1 = x + (size_t)(m0+rowA+64)*K + c4;
    const float* pB0 = g_Wc + (size_t)(n0+rowA)*K + c4;
    const float* pB1 = g_Wc + (size_t)(n0+rowA+64)*K + c4;
    float4 a0 = *(const float4*)pA0, a1 = *(const float4*)pA1;
    float4 b0 = *(const float4*)pB0, b1 = *(const float4*)pB1;
    sts_tile(As[0], rowA, c4, a0, a1); sts_tile(Bs[0], rowA, c4, b0, b1);
    for (int t = 0; t < NT; t++){
        int cur = t & 1; bool more = (t+1 < NT);
        __syncthreads();
        if (more){ int off = (t+1)*BK;
            a0 = *(const float4*)(pA0+off); a1 = *(const float4*)(pA1+off);
            b0 = *(const float4*)(pB0+off); b1 = *(const float4*)(pB1+off); }
#pragma unroll
        for (int k = 0; k < BK; k++){
            float4 fa0 = *(const float4*)&As[cur][k][ra];
            float4 fa1 = *(const float4*)&As[cur][k][ra+64];
            ulonglong2 fb0 = *(const ulonglong2*)&Bs[cur][k][cb];
            ulonglong2 fb1 = *(const ulonglong2*)&Bs[cur][k][cb+64];
            float av[8] = {fa0.x, fa0.y, fa0.z, fa0.w, fa1.x, fa1.y, fa1.z, fa1.w};
#pragma unroll
            for (int i = 0; i < 8; i++){ ull ap = pk2(av[i]);
                fma2(acc[i][0], ap, fb0.x); fma2(acc[i][1], ap, fb0.y);
                fma2(acc[i][2], ap, fb1.x); fma2(acc[i][3], ap, fb1.y); }
        }
        if (more){ sts_tile(As[cur^1], rowA, c4, a0, a1); sts_tile(Bs[cur^1], rowA, c4, b0, b1); }
    }
#pragma unroll
    for (int i = 0; i < 8; i++){ int r = m0 + ri_of(ra, i);
#pragma unroll
        for (int j = 0; j < 4; j++){ int c = n0 + cj_of(cb, j);
            float2 v = upk2(acc[i][j]); v.x += g_bc[c]; v.y += g_bc[c+1];
            *(float2*)&g_attn[(size_t)r*DN + c] = v; } }
}

// ============ LN(attn+state) -> fp16 hi/lo fragment image ============
__global__ __launch_bounds__(128)
void ln_split_kernel(const float* __restrict__ x, const float* __restrict__ na,
                     const float* __restrict__ lng, const float* __restrict__ lnb){
    int rr = blockIdx.x, tx = threadIdx.x, r = rr & (BRN-1);
    const float* sp = (rr < BRN) ? (na + tx*4) : (x + (size_t)r*DN + tx*4);
    float4 a = *(const float4*)&g_attn[(size_t)r*DN + tx*4];
    float4 s = *(const float4*)sp;
    float vx = a.x+s.x, vy = a.y+s.y, vz = a.z+s.z, vw = a.w+s.w;
    float sum = vx+vy+vz+vw, sq = vx*vx+vy*vy+vz*vz+vw*vw;
#pragma unroll
    for (int o = 16; o > 0; o >>= 1){
        sum += __shfl_xor_sync(0xffffffff, sum, o); sq += __shfl_xor_sync(0xffffffff, sq, o); }
    __shared__ float sh[8];
    int w = tx >> 5;
    if ((tx & 31) == 0){ sh[w] = sum; sh[4+w] = sq; }
    __syncthreads();
    float ts = sh[0]+sh[1]+sh[2]+sh[3], ts2 = sh[4]+sh[5]+sh[6]+sh[7];
    float mean = ts*(1.f/DN), rstd = rsqrtf(ts2*(1.f/DN) - mean*mean + 1e-5f);
    float4 g = *(const float4*)&lng[tx*4];
    float4 b = *(const float4*)&lnb[tx*4];
    float o0 = fmaf((vx-mean)*rstd, g.x, b.x), o1 = fmaf((vy-mean)*rstd, g.y, b.y);
    float o2 = fmaf((vz-mean)*rstd, g.z, b.z), o3 = fmaf((vw-mean)*rstd, g.w, b.w);
    uint32_t h0, l0, h1, l1; hsplit2(o0, o1, h0, l0); hsplit2(o2, o3, h1, l1);
    int k = tx*4; const int KT = DN/16;
    *(uint32_t*)(g_himg + aoff(rr, k,   0, KT)) = h0;
    *(uint32_t*)(g_himg + aoff(rr, k,   1, KT)) = l0;
    *(uint32_t*)(g_himg + aoff(rr, k+2, 0, KT)) = h1;
    *(uint32_t*)(g_himg + aoff(rr, k+2, 1, KT)) = l1;
}

// ============ weight -> fragment image ============
__global__ void wsplit_kernel(const float* __restrict__ w, int which, int K, int ksh){
    uint8_t* img = which ? g_w2img : g_w1img;
    int id = blockIdx.x*256 + threadIdx.x;
    int kp = id & ((K >> 1) - 1), n = id >> ksh, k = kp*2;
    float xv = w[(size_t)n*K + k], yv = w[(size_t)n*K + k + 1];
    uint32_t hi, lo; hsplit2(xv, yv, hi, lo);
    int KT = K >> 4;
    *(uint32_t*)(img + boff(n, k, 0, KT)) = hi;
    *(uint32_t*)(img + boff(n, k, 1, KT)) = lo;
}

// ============ HMMA mainloop: 128x128 block, 8 warps (2x4), fp16x3 ============
__device__ __forceinline__ void issue_cp(char* smbuf, const uint8_t* A, const uint8_t* B, int tid){
    uint32_t d = smem_u32(smbuf) + (uint32_t)tid*32u;
    cpa16(d,      A + tid*32); cpa16(d + 16,        A + tid*32 + 16);
    cpa16(d+8192, B + tid*32); cpa16(d + 8192 + 16, B + tid*32 + 16);
    asm volatile("cp.async.commit_group;" ::: "memory");
}
__device__ __forceinline__ void mloop(const uint8_t* Ab, const uint8_t* Bb, int KT,
                                      char* sm, float acc[4][4][4], int tid, int wm, int wn, int lane){
    issue_cp(sm, Ab, Bb, tid);
    for (int t = 0; t < KT; t++){
        int cur = t & 1;
        if (t+1 < KT){
            issue_cp(sm + (cur^1)*16384, Ab + (size_t)(t+1)*8192, Bb + (size_t)(t+1)*8192, tid);
            asm volatile("cp.async.wait_group 1;" ::: "memory");
        } else asm volatile("cp.async.wait_group 0;" ::: "memory");
        __syncthreads();
        char* base = sm + cur*16384;
        uint32_t ah[4][4], al[4][4];
#pragma unroll
        for (int mi = 0; mi < 4; mi++){
            *(uint4*)ah[mi] = *(const uint4*)(base + (((wm*4+mi))*32 + lane)*16);
            *(uint4*)al[mi] = *(const uint4*)(base + ((8 + wm*4+mi)*32 + lane)*16);
        }
#pragma unroll
        for (int nj = 0; nj < 4; nj++){
            uint4 bv = *(const uint4*)(base + 8192 + ((wn*4+nj)*32 + lane)*16);
#pragma unroll
            for (int mi = 0; mi < 4; mi++){
                hmma(acc[mi][nj], ah[mi], bv.x, bv.y);
                hmma(acc[mi][nj], ah[mi], bv.z, bv.w);
                hmma(acc[mi][nj], al[mi], bv.x, bv.y);
            }
        }
        __syncthreads();
    }
}

// ============ g = relu(h @ w1T + b1) ============
__global__ __launch_bounds__(256, 1)
void gemm_g_tc(const float* __restrict__ b1){
    __shared__ __align__(16) char sm[32768];
    int tid = threadIdx.x, wid = tid >> 5, lane = tid & 31, wm = wid & 1, wn = wid >> 1;
    int m0 = blockIdx.y*128, n0 = blockIdx.x*128;
    float acc[4][4][4] = {};
    mloop(g_himg + (size_t)blockIdx.y*(DN/16)*8192, g_w1img + (size_t)blockIdx.x*(DN/16)*8192,
          DN/16, sm, acc, tid, wm, wn, lane);
    int gid = lane >> 2, tig = lane & 3; const int KT = HN/16;
#pragma unroll
    for (int mi = 0; mi < 4; mi++)
#pragma unroll
        for (int nj = 0; nj < 4; nj++){
            int col = n0 + wn*32 + nj*8 + tig*2;
            float bx = __ldg(&b1[col]), by = __ldg(&b1[col+1]);
#pragma unroll
            for (int h = 0; h < 2; h++){
                int row = m0 + wm*64 + mi*16 + gid + h*8;
                float v0 = fmaxf(acc[mi][nj][2*h] + bx, 0.f);
                float v1 = fmaxf(acc[mi][nj][2*h+1] + by, 0.f);
                uint32_t hi, lo; hsplit2(v0, v1, hi, lo);
                *(uint32_t*)(g_gimg + aoff(row, col, 0, KT)) = hi;
                *(uint32_t*)(g_gimg + aoff(row, col, 1, KT)) = lo;
            }
        }
}

// ============ logits: fused online max/argmax/sumexp ============
__global__ __launch_bounds__(256, 1)
void logits_tc(const float* __restrict__ b2){
    __shared__ __align__(16) char sm[32768];
    int tid = threadIdx.x, wid = tid >> 5, lane = tid & 31, wm = wid & 1, wn = wid >> 1;
    int gid = lane >> 2, tig = lane & 3, m0 = blockIdx.x*128;
    float t1[8], su[8]; int ag[8];
#pragma unroll
    for (int s = 0; s < 8; s++){ t1[s] = -1e30f; su[s] = 0.f; ag[s] = 0; }
    const uint8_t* Ab = g_gimg + (size_t)blockIdx.x*(HN/16)*8192;
    for (int nt = 0; nt < NRELN/128; nt++){
        float acc[4][4][4] = {};
        mloop(Ab, g_w2img + (size_t)nt*(HN/16)*8192, HN/16, sm, acc, tid, wm, wn, lane);
#pragma unroll
        for (int nj = 0; nj < 4; nj++){
            int cb = nt*128 + wn*32 + nj*8 + tig*2;
            float bx = __ldg(&b2[cb]), by = __ldg(&b2[cb+1]);
#pragma unroll
            for (int mi = 0; mi < 4; mi++)
#pragma unroll
                for (int h = 0; h < 2; h++){
                    int s = mi*2 + h;
                    float l0 = acc[mi][nj][2*h] + bx, l1 = acc[mi][nj][2*h+1] + by;
                    if (l0 > t1[s]){ su[s] = fmaf(su[s], fexp(t1[s]-l0), 1.f); t1[s] = l0; ag[s] = cb; }
                    else su[s] += fexp(l0 - t1[s]);
                    if (l1 > t1[s]){ su[s] = fmaf(su[s], fexp(t1[s]-l1), 1.f); t1[s] = l1; ag[s] = cb+1; }
                    else su[s] += fexp(l1 - t1[s]);
                }
        }
    }
    float* smax = (float*)sm; float* ssum = smax + 2048; int* sarg = (int*)(ssum + 2048);
    int sc = wn*4 + tig;
#pragma unroll
    for (int mi = 0; mi < 4; mi++)
#pragma unroll
        for (int h = 0; h < 2; h++){
            int row = wm*64 + mi*16 + gid + h*8, s = mi*2 + h;
            smax[row*16 + sc] = t1[s]; ssum[row*16 + sc] = su[s]; sarg[row*16 + sc] = ag[s];
        }
    __syncthreads();
    if (tid < 128){
        int row = tid; float bm = -1e30f; int ba = 1 << 30;
#pragma unroll
        for (int i = 0; i < 16; i++){
            float m = smax[row*16 + i]; int a = sarg[row*16 + i];
            if (m > bm || (m == bm && a < ba)){ bm = m; ba = a; }
        }
        float ssv = 0.f;
#pragma unroll
        for (int i = 0; i < 16; i++) ssv = fmaf(ssum[row*16 + i], __expf(smax[row*16 + i] - bm), ssv);
        g_arg[m0 + row] = ba; g_sum[m0 + row] = ssv;
    }
}

// ============ finalize ============
__global__ void finalize_kernel(float* __restrict__ out){
    int r = blockIdx.x*256 + threadIdx.x;
    if (r >= BRN) return;
    float m0 = 1.f / g_sum[r], m1 = 1.f / g_sum[BRN + r];
    int i0 = g_arg[r], i1 = g_arg[BRN + r];
    bool c0 = (i0 != 0) && (m0 >= 0.1f);
    bool c1 = c0 && (i1 != 0) && (m1 >= 0.1f);
    out[r] = c0 ? (c1 ? m0*m1 : m0) : 0.f;
    out[BRN + r] = (float)i0; out[2*BRN + r] = (float)i1;
    out[3*BRN + r] = (float)((int)c0 + (int)c1);
}

extern "C" void kernel_launch(void* const* d_in, const int* in_sizes, int n_in,
                              void* d_out, int out_size){
    const float* x    = (const float*)d_in[0];
    const float* na   = (const float*)d_in[1];
    const float* v_w  = (const float*)d_in[2];
    const float* v_b  = (const float*)d_in[3];
    const float* o_w  = (const float*)d_in[4];
    const float* o_b  = (const float*)d_in[5];
    const float* ln_g = (const float*)d_in[6];
    const float* ln_b = (const float*)d_in[7];
    const float* w1   = (const float*)d_in[8];
    const float* b1   = (const float*)d_in[9];
    const float* w2   = (const float*)d_in[10];
    const float* b2   = (const float*)d_in[11];
    float* out = (float*)d_out;

    combine_w_kernel<<<DN, 256>>>(o_w, v_w, v_b, o_b);
    wsplit_kernel<<<(HN*DN/2)/256, 256>>>(w1, 0, DN, 8);
    wsplit_kernel<<<((size_t)NRELN*HN/2)/256, 256>>>(w2, 1, HN, 9);
    gemm_attn_kernel<<<dim3(DN/128, BRN/128), 256>>>(x);
    ln_split_kernel<<<ROWS2, 128>>>(x, na, ln_g, ln_b);
    gemm_g_tc<<<dim3(HN/128, ROWS2/128), 256>>>(b1);
    logits_tc<<<ROWS2/128, 256>>>(b2);
    finalize_kernel<<<BRN/256, 256>>>(out);
}

// round 7
// speedup vs baseline: 4.0136x; 1.3112x over previous
#include <cuda_runtime.h>
#include <cuda_fp16.h>
#include <cstdint>

#define BRN 32768
#define DN 512
#define HN 1024
#define NRELN 2048
#define ROWS2 65536
#define BK 16
#define BMP 132
typedef unsigned long long ull;

__device__ float g_attn[(size_t)BRN * DN];
__device__ float g_Wc[DN * DN];
__device__ float g_bc[DN];
__device__ uint8_t g_himg[(size_t)(ROWS2/128)*(DN/16)*8192];
__device__ uint8_t g_gimg[(size_t)(ROWS2/128)*(HN/16)*8192];
__device__ uint8_t g_w1img[(size_t)(HN/128)*(DN/16)*8192];
__device__ uint8_t g_w2img[(size_t)(NRELN/128)*(HN/16)*8192];
__device__ float g_sum[ROWS2];
__device__ int   g_arg[ROWS2];

__device__ __forceinline__ ull pk2(float x){ ull r; asm("mov.b64 %0, {%1, %1};" : "=l"(r) : "f"(x)); return r; }
__device__ __forceinline__ void fma2(ull& d, ull a, ull b){ asm("fma.rn.f32x2 %0, %1, %2, %0;" : "+l"(d) : "l"(a), "l"(b)); }
__device__ __forceinline__ float2 upk2(ull v){ float2 f; asm("mov.b64 {%0, %1}, %2;" : "=f"(f.x), "=f"(f.y) : "l"(v)); return f; }
__device__ __forceinline__ uint32_t smem_u32(const void* p){
    uint32_t a; asm("{ .reg .u64 t; cvta.to.shared.u64 t, %1; cvt.u32.u64 %0, t; }" : "=r"(a) : "l"(p)); return a;
}
__device__ __forceinline__ void cpa16(uint32_t d, const void* s){
    asm volatile("cp.async.cg.shared.global [%0],[%1],16;" :: "r"(d), "l"(s));
}
__device__ __forceinline__ void hmma(float* c, const uint32_t* a, uint32_t b0, uint32_t b1){
    asm volatile("mma.sync.aligned.m16n8k16.row.col.f32.f16.f16.f32 {%0,%1,%2,%3},{%4,%5,%6,%7},{%8,%9},{%0,%1,%2,%3};"
        : "+f"(c[0]), "+f"(c[1]), "+f"(c[2]), "+f"(c[3])
        : "r"(a[0]), "r"(a[1]), "r"(a[2]), "r"(a[3]), "r"(b0), "r"(b1));
}
__device__ __forceinline__ float fexp(float x){
    x = fmaxf(x, -80.f);
    return __uint_as_float((uint32_t)(int)(fmaf(x, 12102203.0f, 1064866805.0f)));
}
__device__ __forceinline__ void hsplit2(float x, float y, uint32_t& hi, uint32_t& lo){
    __half hx = __float2half_rn(x), hy = __float2half_rn(y);
    __half lx = __float2half_rn(x - __half2float(hx)), ly = __float2half_rn(y - __half2float(hy));
    hi = (uint32_t)__half_as_ushort(hx) | ((uint32_t)__half_as_ushort(hy) << 16);
    lo = (uint32_t)__half_as_ushort(lx) | ((uint32_t)__half_as_ushort(ly) << 16);
}
// fragment-image byte offsets (A: rows x k, B: n x k), tile = 128x16, 2 planes, 8KB
__device__ __forceinline__ size_t aoff(int row, int k, int plane, int KT){
    int mblk = row >> 7, mi = (row >> 4) & 7, g = row & 7, rb = (row >> 3) & 1;
    int kt = k >> 4, tg = (k >> 1) & 3, kb = (k >> 3) & 1;
    return (size_t)(mblk * KT + kt) * 8192 + (size_t)((((plane*8 + mi)*32 + g*4 + tg)*4 + rb + 2*kb) * 4);
}
__device__ __forceinline__ size_t boff(int n, int k, int plane, int KT){
    int nblk = n >> 7, nj = (n >> 3) & 15, g = n & 7;
    int kt = k >> 4, tg = (k >> 1) & 3, kb = (k >> 3) & 1;
    return (size_t)(nblk * KT + kt) * 8192 + (size_t)(((((nj*32 + g*4 + tg)*2 + plane)*2 + kb)) * 4);
}

// ============ combine W ============
__global__ void combine_w_kernel(const float* __restrict__ o_w, const float* __restrict__ v_w,
                                 const float* __restrict__ v_b, const float* __restrict__ o_b){
    int i = blockIdx.x, tx = threadIdx.x;
    __shared__ float orow[DN];
    for (int k = tx; k < DN; k += 256) orow[k] = o_w[i*DN + k];
    __syncthreads();
    float a0 = 0.f, a1 = 0.f;
    for (int k = 0; k < DN; k++){ float a = orow[k];
        a0 = fmaf(a, v_w[k*DN + tx], a0); a1 = fmaf(a, v_w[k*DN + tx + 256], a1); }
    g_Wc[i*DN + tx] = a0; g_Wc[i*DN + tx + 256] = a1;
    if (tx == 0){ float b = o_b[i];
        for (int k = 0; k < DN; k++) b = fmaf(orow[k], v_b[k], b);
        g_bc[i] = b; }
}

// ============ attn = x @ WcT + bc (exact fp32, FFMA2) ============
__device__ __forceinline__ void sts_tile(float dst[BK][BMP], int rowA, int c4, float4 p0, float4 p1){
    dst[c4+0][rowA] = p0.x; dst[c4+1][rowA] = p0.y; dst[c4+2][rowA] = p0.z; dst[c4+3][rowA] = p0.w;
    dst[c4+0][rowA+64] = p1.x; dst[c4+1][rowA+64] = p1.y; dst[c4+2][rowA+64] = p1.z; dst[c4+3][rowA+64] = p1.w;
}
__device__ __forceinline__ int ri_of(int ra, int i){ return ra + (i < 4 ? i : 60 + i); }
__device__ __forceinline__ int cj_of(int cb, int j){ return cb + (j < 2 ? 2*j : 60 + 2*j); }

__global__ __launch_bounds__(256, 2)
void gemm_attn_kernel(const float* __restrict__ x){
    __shared__ __align__(16) float As[2][BK][BMP];
    __shared__ __align__(16) float Bs[2][BK][BMP];
    int tx = threadIdx.x, m0 = blockIdx.y*128, n0 = blockIdx.x*128;
    int ra = (tx >> 4)*4, cb = (tx & 15)*4;
    ull acc[8][4];
#pragma unroll
    for (int i = 0; i < 8; i++)
#pragma unroll
        for (int j = 0; j < 4; j++) acc[i][j] = 0ull;
    const int K = DN, NT = K/BK;
    const int rowA = tx >> 2, c4 = (tx & 3)*4;
    const float* pA0 = x + (size_t)(m0+rowA)*K + c4;
    const float* pA1 = x + (size_t)(m0+rowA+64)*K + c4;
    const float* pB0 = g_Wc + (size_t)(n0+rowA)*K + c4;
    const float* pB1 = g_Wc + (size_t)(n0+rowA+64)*K + c4;
    float4 a0 = *(const float4*)pA0, a1 = *(const float4*)pA1;
    float4 b0 = *(const float4*)pB0, b1 = *(const float4*)pB1;
    sts_tile(As[0], rowA, c4, a0, a1); sts_tile(Bs[0], rowA, c4, b0, b1);
    for (int t = 0; t < NT; t++){
        int cur = t & 1; bool more = (t+1 < NT);
        __syncthreads();
        if (more){ int off = (t+1)*BK;
            a0 = *(const float4*)(pA0+off); a1 = *(const float4*)(pA1+off);
            b0 = *(const float4*)(pB0+off); b1 = *(const float4*)(pB1+off); }
#pragma unroll
        for (int k = 0; k < BK; k++){
            float4 fa0 = *(const float4*)&As[cur][k][ra];
            float4 fa1 = *(const float4*)&As[cur][k][ra+64];
            ulonglong2 fb0 = *(const ulonglong2*)&Bs[cur][k][cb];
            ulonglong2 fb1 = *(const ulonglong2*)&Bs[cur][k][cb+64];
            float av[8] = {fa0.x, fa0.y, fa0.z, fa0.w, fa1.x, fa1.y, fa1.z, fa1.w};
#pragma unroll
            for (int i = 0; i < 8; i++){ ull ap = pk2(av[i]);
                fma2(acc[i][0], ap, fb0.x); fma2(acc[i][1], ap, fb0.y);
                fma2(acc[i][2], ap, fb1.x); fma2(acc[i][3], ap, fb1.y); }
        }
        if (more){ sts_tile(As[cur^1], rowA, c4, a0, a1); sts_tile(Bs[cur^1], rowA, c4, b0, b1); }
    }
#pragma unroll
    for (int i = 0; i < 8; i++){ int r = m0 + ri_of(ra, i);
#pragma unroll
        for (int j = 0; j < 4; j++){ int c = n0 + cj_of(cb, j);
            float2 v = upk2(acc[i][j]); v.x += g_bc[c]; v.y += g_bc[c+1];
            *(float2*)&g_attn[(size_t)r*DN + c] = v; } }
}

// ============ LN(attn+state) -> fp16 hi/lo fragment image ============
__global__ __launch_bounds__(128)
void ln_split_kernel(const float* __restrict__ x, const float* __restrict__ na,
                     const float* __restrict__ lng, const float* __restrict__ lnb){
    int rr = blockIdx.x, tx = threadIdx.x, r = rr & (BRN-1);
    const float* sp = (rr < BRN) ? (na + tx*4) : (x + (size_t)r*DN + tx*4);
    float4 a = *(const float4*)&g_attn[(size_t)r*DN + tx*4];
    float4 s = *(const float4*)sp;
    float vx = a.x+s.x, vy = a.y+s.y, vz = a.z+s.z, vw = a.w+s.w;
    float sum = vx+vy+vz+vw, sq = vx*vx+vy*vy+vz*vz+vw*vw;
#pragma unroll
    for (int o = 16; o > 0; o >>= 1){
        sum += __shfl_xor_sync(0xffffffff, sum, o); sq += __shfl_xor_sync(0xffffffff, sq, o); }
    __shared__ float sh[8];
    int w = tx >> 5;
    if ((tx & 31) == 0){ sh[w] = sum; sh[4+w] = sq; }
    __syncthreads();
    float ts = sh[0]+sh[1]+sh[2]+sh[3], ts2 = sh[4]+sh[5]+sh[6]+sh[7];
    float mean = ts*(1.f/DN), rstd = rsqrtf(ts2*(1.f/DN) - mean*mean + 1e-5f);
    float4 g = *(const float4*)&lng[tx*4];
    float4 b = *(const float4*)&lnb[tx*4];
    float o0 = fmaf((vx-mean)*rstd, g.x, b.x), o1 = fmaf((vy-mean)*rstd, g.y, b.y);
    float o2 = fmaf((vz-mean)*rstd, g.z, b.z), o3 = fmaf((vw-mean)*rstd, g.w, b.w);
    uint32_t h0, l0, h1, l1; hsplit2(o0, o1, h0, l0); hsplit2(o2, o3, h1, l1);
    int k = tx*4; const int KT = DN/16;
    *(uint32_t*)(g_himg + aoff(rr, k,   0, KT)) = h0;
    *(uint32_t*)(g_himg + aoff(rr, k,   1, KT)) = l0;
    *(uint32_t*)(g_himg + aoff(rr, k+2, 0, KT)) = h1;
    *(uint32_t*)(g_himg + aoff(rr, k+2, 1, KT)) = l1;
}

// ============ weight -> fragment image ============
__global__ void wsplit_kernel(const float* __restrict__ w, int which, int K, int ksh){
    uint8_t* img = which ? g_w2img : g_w1img;
    int id = blockIdx.x*256 + threadIdx.x;
    int kp = id & ((K >> 1) - 1), n = id >> ksh, k = kp*2;
    float xv = w[(size_t)n*K + k], yv = w[(size_t)n*K + k + 1];
    uint32_t hi, lo; hsplit2(xv, yv, hi, lo);
    int KT = K >> 4;
    *(uint32_t*)(img + boff(n, k, 0, KT)) = hi;
    *(uint32_t*)(img + boff(n, k, 1, KT)) = lo;
}

// ============ HMMA mainloop: 128x128 block, 8 warps (2x4), fp16x3 ============
// 3-stage cp.async pipeline, one __syncthreads per k-tile (+1 trailing).
__device__ __forceinline__ void issue_cp(char* smbuf, const uint8_t* A, const uint8_t* B, int tid){
    uint32_t d = smem_u32(smbuf) + (uint32_t)tid*32u;
    cpa16(d,      A + tid*32); cpa16(d + 16,        A + tid*32 + 16);
    cpa16(d+8192, B + tid*32); cpa16(d + 8192 + 16, B + tid*32 + 16);
    asm volatile("cp.async.commit_group;" ::: "memory");
}
__device__ __forceinline__ void mloop(const uint8_t* Ab, const uint8_t* Bb, int KT,
                                      char* sm, float acc[4][4][4], int tid, int wm, int wn, int lane){
    issue_cp(sm,         Ab,        Bb,        tid);
    issue_cp(sm + 16384, Ab + 8192, Bb + 8192, tid);
    for (int t = 0; t < KT; t++){
        if (t + 1 < KT) asm volatile("cp.async.wait_group 1;" ::: "memory");
        else            asm volatile("cp.async.wait_group 0;" ::: "memory");
        __syncthreads();
        if (t + 2 < KT)
            issue_cp(sm + ((t+2)%3)*16384, Ab + (size_t)(t+2)*8192, Bb + (size_t)(t+2)*8192, tid);
        char* base = sm + (t%3)*16384;
        uint32_t ah[4][4], al[4][4];
#pragma unroll
        for (int mi = 0; mi < 4; mi++){
            *(uint4*)ah[mi] = *(const uint4*)(base + (((wm*4+mi))*32 + lane)*16);
            *(uint4*)al[mi] = *(const uint4*)(base + ((8 + wm*4+mi)*32 + lane)*16);
        }
#pragma unroll
        for (int nj = 0; nj < 4; nj++){
            uint4 bv = *(const uint4*)(base + 8192 + ((wn*4+nj)*32 + lane)*16);
#pragma unroll
            for (int mi = 0; mi < 4; mi++){
                hmma(acc[mi][nj], ah[mi], bv.x, bv.y);
                hmma(acc[mi][nj], ah[mi], bv.z, bv.w);
                hmma(acc[mi][nj], al[mi], bv.x, bv.y);
            }
        }
    }
    __syncthreads();   // protect stage buffers from next mloop / smem reuse
}

// ============ g = relu(h @ w1T + b1) ============
__global__ __launch_bounds__(256, 2)
void gemm_g_tc(const float* __restrict__ b1){
    __shared__ __align__(16) char sm[49152];
    int tid = threadIdx.x, wid = tid >> 5, lane = tid & 31, wm = wid & 1, wn = wid >> 1;
    int m0 = blockIdx.y*128, n0 = blockIdx.x*128;
    float acc[4][4][4] = {};
    mloop(g_himg + (size_t)blockIdx.y*(DN/16)*8192, g_w1img + (size_t)blockIdx.x*(DN/16)*8192,
          DN/16, sm, acc, tid, wm, wn, lane);
    int gid = lane >> 2, tig = lane & 3; const int KT = HN/16;
#pragma unroll
    for (int mi = 0; mi < 4; mi++)
#pragma unroll
        for (int nj = 0; nj < 4; nj++){
            int col = n0 + wn*32 + nj*8 + tig*2;
            float bx = __ldg(&b1[col]), by = __ldg(&b1[col+1]);
#pragma unroll
            for (int h = 0; h < 2; h++){
                int row = m0 + wm*64 + mi*16 + gid + h*8;
                float v0 = fmaxf(acc[mi][nj][2*h] + bx, 0.f);
                float v1 = fmaxf(acc[mi][nj][2*h+1] + by, 0.f);
                uint32_t hi, lo; hsplit2(v0, v1, hi, lo);
                *(uint32_t*)(g_gimg + aoff(row, col, 0, KT)) = hi;
                *(uint32_t*)(g_gimg + aoff(row, col, 1, KT)) = lo;
            }
        }
}

// ============ logits: fused online max/argmax/sumexp ============
__global__ __launch_bounds__(256, 2)
void logits_tc(const float* __restrict__ b2){
    __shared__ __align__(16) char sm[49152];
    int tid = threadIdx.x, wid = tid >> 5, lane = tid & 31, wm = wid & 1, wn = wid >> 1;
    int gid = lane >> 2, tig = lane & 3, m0 = blockIdx.x*128;
    float t1[8], su[8]; int ag[8];
#pragma unroll
    for (int s = 0; s < 8; s++){ t1[s] = -1e30f; su[s] = 0.f; ag[s] = 0; }
    const uint8_t* Ab = g_gimg + (size_t)blockIdx.x*(HN/16)*8192;
    for (int nt = 0; nt < NRELN/128; nt++){
        float acc[4][4][4] = {};
        mloop(Ab, g_w2img + (size_t)nt*(HN/16)*8192, HN/16, sm, acc, tid, wm, wn, lane);
#pragma unroll
        for (int nj = 0; nj < 4; nj++){
            int cb = nt*128 + wn*32 + nj*8 + tig*2;
            float bx = __ldg(&b2[cb]), by = __ldg(&b2[cb+1]);
#pragma unroll
            for (int mi = 0; mi < 4; mi++)
#pragma unroll
                for (int h = 0; h < 2; h++){
                    int s = mi*2 + h;
                    float l0 = acc[mi][nj][2*h] + bx, l1 = acc[mi][nj][2*h+1] + by;
                    if (l0 > t1[s]){ su[s] = fmaf(su[s], fexp(t1[s]-l0), 1.f); t1[s] = l0; ag[s] = cb; }
                    else su[s] += fexp(l0 - t1[s]);
                    if (l1 > t1[s]){ su[s] = fmaf(su[s], fexp(t1[s]-l1), 1.f); t1[s] = l1; ag[s] = cb+1; }
                    else su[s] += fexp(l1 - t1[s]);
                }
        }
    }
    float* smax = (float*)sm; float* ssum = smax + 2048; int* sarg = (int*)(ssum + 2048);
    int sc = wn*4 + tig;
#pragma unroll
    for (int mi = 0; mi < 4; mi++)
#pragma unroll
        for (int h = 0; h < 2; h++){
            int row = wm*64 + mi*16 + gid + h*8, s = mi*2 + h;
            smax[row*16 + sc] = t1[s]; ssum[row*16 + sc] = su[s]; sarg[row*16 + sc] = ag[s];
        }
    __syncthreads();
    if (tid < 128){
        int row = tid; float bm = -1e30f; int ba = 1 << 30;
#pragma unroll
        for (int i = 0; i < 16; i++){
            float m = smax[row*16 + i]; int a = sarg[row*16 + i];
            if (m > bm || (m == bm && a < ba)){ bm = m; ba = a; }
        }
        float ssv = 0.f;
#pragma unroll
        for (int i = 0; i < 16; i++) ssv = fmaf(ssum[row*16 + i], __expf(smax[row*16 + i] - bm), ssv);
        g_arg[m0 + row] = ba; g_sum[m0 + row] = ssv;
    }
}

// ============ finalize ============
__global__ void finalize_kernel(float* __restrict__ out){
    int r = blockIdx.x*256 + threadIdx.x;
    if (r >= BRN) return;
    float m0 = 1.f / g_sum[r], m1 = 1.f / g_sum[BRN + r];
    int i0 = g_arg[r], i1 = g_arg[BRN + r];
    bool c0 = (i0 != 0) && (m0 >= 0.1f);
    bool c1 = c0 && (i1 != 0) && (m1 >= 0.1f);
    out[r] = c0 ? (c1 ? m0*m1 : m0) : 0.f;
    out[BRN + r] = (float)i0; out[2*BRN + r] = (float)i1;
    out[3*BRN + r] = (float)((int)c0 + (int)c1);
}

extern "C" void kernel_launch(void* const* d_in, const int* in_sizes, int n_in,
                              void* d_out, int out_size){
    const float* x    = (const float*)d_in[0];
    const float* na   = (const float*)d_in[1];
    const float* v_w  = (const float*)d_in[2];
    const float* v_b  = (const float*)d_in[3];
    const float* o_w  = (const float*)d_in[4];
    const float* o_b  = (const float*)d_in[5];
    const float* ln_g = (const float*)d_in[6];
    const float* ln_b = (const float*)d_in[7];
    const float* w1   = (const float*)d_in[8];
    const float* b1   = (const float*)d_in[9];
    const float* w2   = (const float*)d_in[10];
    const float* b2   = (const float*)d_in[11];
    float* out = (float*)d_out;

    combine_w_kernel<<<DN, 256>>>(o_w, v_w, v_b, o_b);
    wsplit_kernel<<<(HN*DN/2)/256, 256>>>(w1, 0, DN, 8);
    wsplit_kernel<<<((size_t)NRELN*HN/2)/256, 256>>>(w2, 1, HN, 9);
    gemm_attn_kernel<<<dim3(DN/128, BRN/128), 256>>>(x);
    ln_split_kernel<<<ROWS2, 128>>>(x, na, ln_g, ln_b);
    gemm_g_tc<<<dim3(HN/128, ROWS2/128), 256>>>(b1);
    logits_tc<<<ROWS2/128, 256>>>(b2);
    finalize_kernel<<<BRN/256, 256>>>(out);
}

// round 8
// speedup vs baseline: 4.3498x; 1.0837x over previous
#include <cuda_runtime.h>
#include <cuda_fp16.h>
#include <cstdint>

#define BRN 32768
#define DN 512
#define HN 1024
#define NRELN 2048
#define ROWS2 65536

__device__ float g_attn[(size_t)BRN * DN];
__device__ float g_Wc[DN * DN];
__device__ float g_bc[DN];
__device__ uint8_t g_ximg[(size_t)(BRN/128)*(DN/16)*8192];
__device__ uint8_t g_wcimg[(size_t)(DN/128)*(DN/16)*8192];
__device__ uint8_t g_himg[(size_t)(ROWS2/128)*(DN/16)*8192];
__device__ uint8_t g_gimg[(size_t)(ROWS2/128)*(HN/16)*8192];
__device__ uint8_t g_w1img[(size_t)(HN/128)*(DN/16)*8192];
__device__ uint8_t g_w2img[(size_t)(NRELN/128)*(HN/16)*8192];
__device__ float g_sum[ROWS2];
__device__ int   g_arg[ROWS2];

__device__ __forceinline__ uint32_t smem_u32(const void* p){
    uint32_t a; asm("{ .reg .u64 t; cvta.to.shared.u64 t, %1; cvt.u32.u64 %0, t; }" : "=r"(a) : "l"(p)); return a;
}
__device__ __forceinline__ void cpa16(uint32_t d, const void* s){
    asm volatile("cp.async.cg.shared.global [%0],[%1],16;" :: "r"(d), "l"(s));
}
__device__ __forceinline__ void hmma(float* c, const uint32_t* a, uint32_t b0, uint32_t b1){
    asm volatile("mma.sync.aligned.m16n8k16.row.col.f32.f16.f16.f32 {%0,%1,%2,%3},{%4,%5,%6,%7},{%8,%9},{%0,%1,%2,%3};"
        : "+f"(c[0]), "+f"(c[1]), "+f"(c[2]), "+f"(c[3])
        : "r"(a[0]), "r"(a[1]), "r"(a[2]), "r"(a[3]), "r"(b0), "r"(b1));
}
__device__ __forceinline__ float fexp(float x){
    x = fmaxf(x, -80.f);
    return __uint_as_float((uint32_t)(int)(fmaf(x, 12102203.0f, 1064866805.0f)));
}
__device__ __forceinline__ void hsplit2(float x, float y, uint32_t& hi, uint32_t& lo){
    __half hx = __float2half_rn(x), hy = __float2half_rn(y);
    __half lx = __float2half_rn(x - __half2float(hx)), ly = __float2half_rn(y - __half2float(hy));
    hi = (uint32_t)__half_as_ushort(hx) | ((uint32_t)__half_as_ushort(hy) << 16);
    lo = (uint32_t)__half_as_ushort(lx) | ((uint32_t)__half_as_ushort(ly) << 16);
}
// A-image addr: tile(mblk,kt)=8KB; slot16 = ((plane*8+mi8)*32 + g*4 + tg)*16; word = rb + 2*kb
__device__ __forceinline__ size_t aoff(int row, int k, int plane, int KT){
    int mblk = row >> 7, mi = (row >> 4) & 7, g = row & 7, rb = (row >> 3) & 1;
    int kt = k >> 4, tg = (k >> 1) & 3, kb = (k >> 3) & 1;
    return (size_t)(mblk * KT + kt) * 8192 + (size_t)((((plane*8 + mi)*32 + g*4 + tg)*4 + rb + 2*kb) * 4);
}
__device__ __forceinline__ size_t boff(int n, int k, int plane, int KT){
    int nblk = n >> 7, nj = (n >> 3) & 15, g = n & 7;
    int kt = k >> 4, tg = (k >> 1) & 3, kb = (k >> 3) & 1;
    return (size_t)(nblk * KT + kt) * 8192 + (size_t)(((((nj*32 + g*4 + tg)*2 + plane)*2 + kb)) * 4);
}

// ============ combine W ============
__global__ void combine_w_kernel(const float* __restrict__ o_w, const float* __restrict__ v_w,
                                 const float* __restrict__ v_b, const float* __restrict__ o_b){
    int i = blockIdx.x, tx = threadIdx.x;
    __shared__ float orow[DN];
    for (int k = tx; k < DN; k += 256) orow[k] = o_w[i*DN + k];
    __syncthreads();
    float a0 = 0.f, a1 = 0.f;
    for (int k = 0; k < DN; k++){ float a = orow[k];
        a0 = fmaf(a, v_w[k*DN + tx], a0); a1 = fmaf(a, v_w[k*DN + tx + 256], a1); }
    g_Wc[i*DN + tx] = a0; g_Wc[i*DN + tx + 256] = a1;
    if (tx == 0){ float b = o_b[i];
        for (int k = 0; k < DN; k++) b = fmaf(orow[k], v_b[k], b);
        g_bc[i] = b; }
}

// ============ weight -> B fragment image ============
__global__ void wsplit_kernel(const float* __restrict__ w, uint8_t* __restrict__ img, int K, int ksh){
    int id = blockIdx.x*256 + threadIdx.x;
    int kp = id & ((K >> 1) - 1), n = id >> ksh, k = kp*2;
    float xv = w[(size_t)n*K + k], yv = w[(size_t)n*K + k + 1];
    uint32_t hi, lo; hsplit2(xv, yv, hi, lo);
    int KT = K >> 4;
    *(uint32_t*)(img + boff(n, k, 0, KT)) = hi;
    *(uint32_t*)(img + boff(n, k, 1, KT)) = lo;
}

// ============ x -> A fragment image (dense 16B stores) ============
__global__ void xsplit_kernel(const float* __restrict__ x){
    int id = blockIdx.x*256 + threadIdx.x;
    int tg = id & 3, g = (id >> 2) & 7, mi = (id >> 5) & 7, kt = (id >> 8) & 31, mblk = id >> 13;
    uint32_t p0[4], p1[4];
#pragma unroll
    for (int rb = 0; rb < 2; rb++)
#pragma unroll
        for (int kb = 0; kb < 2; kb++){
            int row = mblk*128 + mi*16 + rb*8 + g;
            int k = kt*16 + kb*8 + tg*2;
            float2 v = *(const float2*)&x[(size_t)row*DN + k];
            hsplit2(v.x, v.y, p0[rb + 2*kb], p1[rb + 2*kb]);
        }
    size_t base = (size_t)(mblk*32 + kt)*8192 + (size_t)((mi*32 + g*4 + tg)*16);
    *(uint4*)(g_ximg + base)        = *(uint4*)p0;
    *(uint4*)(g_ximg + base + 4096) = *(uint4*)p1;
}

// ============ HMMA mainloop: 128x128 block, 8 warps (2x4), fp16x3 ============
__device__ __forceinline__ void issue_cp(char* smbuf, const uint8_t* A, const uint8_t* B, int tid){
    uint32_t d = smem_u32(smbuf) + (uint32_t)tid*32u;
    cpa16(d,      A + tid*32); cpa16(d + 16,        A + tid*32 + 16);
    cpa16(d+8192, B + tid*32); cpa16(d + 8192 + 16, B + tid*32 + 16);
    asm volatile("cp.async.commit_group;" ::: "memory");
}
__device__ __forceinline__ void mloop(const uint8_t* Ab, const uint8_t* Bb, int KT,
                                      char* sm, float acc[4][4][4], int tid, int wm, int wn, int lane){
    issue_cp(sm,         Ab,        Bb,        tid);
    issue_cp(sm + 16384, Ab + 8192, Bb + 8192, tid);
    for (int t = 0; t < KT; t++){
        if (t + 1 < KT) asm volatile("cp.async.wait_group 1;" ::: "memory");
        else            asm volatile("cp.async.wait_group 0;" ::: "memory");
        __syncthreads();
        if (t + 2 < KT)
            issue_cp(sm + ((t+2)%3)*16384, Ab + (size_t)(t+2)*8192, Bb + (size_t)(t+2)*8192, tid);
        char* base = sm + (t%3)*16384;
        uint32_t ah[4][4], al[4][4];
#pragma unroll
        for (int mi = 0; mi < 4; mi++){
            *(uint4*)ah[mi] = *(const uint4*)(base + (((wm*4+mi))*32 + lane)*16);
            *(uint4*)al[mi] = *(const uint4*)(base + ((8 + wm*4+mi)*32 + lane)*16);
        }
#pragma unroll
        for (int nj = 0; nj < 4; nj++){
            uint4 bv = *(const uint4*)(base + 8192 + ((wn*4+nj)*32 + lane)*16);
#pragma unroll
            for (int mi = 0; mi < 4; mi++){
                hmma(acc[mi][nj], ah[mi], bv.x, bv.y);
                hmma(acc[mi][nj], ah[mi], bv.z, bv.w);
                hmma(acc[mi][nj], al[mi], bv.x, bv.y);
            }
        }
    }
    __syncthreads();
}

// ============ attn = x @ WcT + bc via HMMA fp16x3, fp32 out ============
__global__ __launch_bounds__(256, 2)
void attn_tc(){
    __shared__ __align__(16) char sm[49152];
    int tid = threadIdx.x, wid = tid >> 5, lane = tid & 31, wm = wid & 1, wn = wid >> 1;
    int gid = lane >> 2, tig = lane & 3;
    int m0 = blockIdx.y*128, n0 = blockIdx.x*128;
    float acc[4][4][4] = {};
    mloop(g_ximg + (size_t)blockIdx.y*(DN/16)*8192, g_wcimg + (size_t)blockIdx.x*(DN/16)*8192,
          DN/16, sm, acc, tid, wm, wn, lane);
#pragma unroll
    for (int mi = 0; mi < 4; mi++)
#pragma unroll
        for (int nj = 0; nj < 4; nj++){
            int col = n0 + wn*32 + nj*8 + tig*2;
            float bx = g_bc[col], by = g_bc[col+1];
#pragma unroll
            for (int h = 0; h < 2; h++){
                int row = m0 + wm*64 + mi*16 + gid + h*8;
                float2 v = {acc[mi][nj][2*h] + bx, acc[mi][nj][2*h+1] + by};
                *(float2*)&g_attn[(size_t)row*DN + col] = v;
            }
        }
}

// ============ LN(attn+state) -> fp16 hi/lo A-image ============
__global__ __launch_bounds__(128)
void ln_split_kernel(const float* __restrict__ x, const float* __restrict__ na,
                     const float* __restrict__ lng, const float* __restrict__ lnb){
    int rr = blockIdx.x, tx = threadIdx.x, r = rr & (BRN-1);
    const float* sp = (rr < BRN) ? (na + tx*4) : (x + (size_t)r*DN + tx*4);
    float4 a = *(const float4*)&g_attn[(size_t)r*DN + tx*4];
    float4 s = *(const float4*)sp;
    float vx = a.x+s.x, vy = a.y+s.y, vz = a.z+s.z, vw = a.w+s.w;
    float sum = vx+vy+vz+vw, sq = vx*vx+vy*vy+vz*vz+vw*vw;
#pragma unroll
    for (int o = 16; o > 0; o >>= 1){
        sum += __shfl_xor_sync(0xffffffff, sum, o); sq += __shfl_xor_sync(0xffffffff, sq, o); }
    __shared__ float sh[8];
    int w = tx >> 5;
    if ((tx & 31) == 0){ sh[w] = sum; sh[4+w] = sq; }
    __syncthreads();
    float ts = sh[0]+sh[1]+sh[2]+sh[3], ts2 = sh[4]+sh[5]+sh[6]+sh[7];
    float mean = ts*(1.f/DN), rstd = rsqrtf(ts2*(1.f/DN) - mean*mean + 1e-5f);
    float4 g = *(const float4*)&lng[tx*4];
    float4 b = *(const float4*)&lnb[tx*4];
    float o0 = fmaf((vx-mean)*rstd, g.x, b.x), o1 = fmaf((vy-mean)*rstd, g.y, b.y);
    float o2 = fmaf((vz-mean)*rstd, g.z, b.z), o3 = fmaf((vw-mean)*rstd, g.w, b.w);
    uint32_t h0, l0, h1, l1; hsplit2(o0, o1, h0, l0); hsplit2(o2, o3, h1, l1);
    int k = tx*4; const int KT = DN/16;
    *(uint32_t*)(g_himg + aoff(rr, k,   0, KT)) = h0;
    *(uint32_t*)(g_himg + aoff(rr, k,   1, KT)) = l0;
    *(uint32_t*)(g_himg + aoff(rr, k+2, 0, KT)) = h1;
    *(uint32_t*)(g_himg + aoff(rr, k+2, 1, KT)) = l1;
}

// ============ g = relu(h @ w1T + b1) ; dense 16B epilogue stores ============
__global__ __launch_bounds__(256, 2)
void gemm_g_tc(const float* __restrict__ b1){
    __shared__ __align__(16) char sm[49152];
    int tid = threadIdx.x, wid = tid >> 5, lane = tid & 31, wm = wid & 1, wn = wid >> 1;
    int gid = lane >> 2, tig = lane & 3;
    int n0 = blockIdx.x*128;
    float acc[4][4][4] = {};
    mloop(g_himg + (size_t)blockIdx.y*(DN/16)*8192, g_w1img + (size_t)blockIdx.x*(DN/16)*8192,
          DN/16, sm, acc, tid, wm, wn, lane);
    const int KT = HN/16;
    float bxv[4], byv[4];
#pragma unroll
    for (int nj = 0; nj < 4; nj++){
        int col = n0 + wn*32 + nj*8 + tig*2;
        bxv[nj] = __ldg(&b1[col]); byv[nj] = __ldg(&b1[col+1]);
    }
#pragma unroll
    for (int mi = 0; mi < 4; mi++)
#pragma unroll
        for (int njp = 0; njp < 2; njp++){
            uint32_t q0[4], q1[4];
#pragma unroll
            for (int q = 0; q < 2; q++){
                int nj = njp*2 + q;
#pragma unroll
                for (int h = 0; h < 2; h++){
                    float v0 = fmaxf(acc[mi][nj][2*h]   + bxv[nj], 0.f);
                    float v1 = fmaxf(acc[mi][nj][2*h+1] + byv[nj], 0.f);
                    hsplit2(v0, v1, q0[h + 2*q], q1[h + 2*q]);
                }
            }
            int kt = (n0 + wn*32 + njp*16) >> 4;
            size_t base = (size_t)(blockIdx.y*KT + kt)*8192
                        + (size_t)(((wm*4 + mi)*32 + gid*4 + tig)*16);
            *(uint4*)(g_gimg + base)        = *(uint4*)q0;
            *(uint4*)(g_gimg + base + 4096) = *(uint4*)q1;
        }
}

// ============ logits: fused online max/argmax/sumexp ============
__global__ __launch_bounds__(256, 2)
void logits_tc(const float* __restrict__ b2){
    __shared__ __align__(16) char sm[49152];
    int tid = threadIdx.x, wid = tid >> 5, lane = tid & 31, wm = wid & 1, wn = wid >> 1;
    int gid = lane >> 2, tig = lane & 3, m0 = blockIdx.x*128;
    float t1[8], su[8]; int ag[8];
#pragma unroll
    for (int s = 0; s < 8; s++){ t1[s] = -1e30f; su[s] = 0.f; ag[s] = 0; }
    const uint8_t* Ab = g_gimg + (size_t)blockIdx.x*(HN/16)*8192;
    for (int nt = 0; nt < NRELN/128; nt++){
        float acc[4][4][4] = {};
        mloop(Ab, g_w2img + (size_t)nt*(HN/16)*8192, HN/16, sm, acc, tid, wm, wn, lane);
#pragma unroll
        for (int nj = 0; nj < 4; nj++){
            int cb = nt*128 + wn*32 + nj*8 + tig*2;
            float bx = __ldg(&b2[cb]), by = __ldg(&b2[cb+1]);
#pragma unroll
            for (int mi = 0; mi < 4; mi++)
#pragma unroll
                for (int h = 0; h < 2; h++){
                    int s = mi*2 + h;
                    float l0 = acc[mi][nj][2*h] + bx, l1 = acc[mi][nj][2*h+1] + by;
                    if (l0 > t1[s]){ su[s] = fmaf(su[s], fexp(t1[s]-l0), 1.f); t1[s] = l0; ag[s] = cb; }
                    else su[s] += fexp(l0 - t1[s]);
                    if (l1 > t1[s]){ su[s] = fmaf(su[s], fexp(t1[s]-l1), 1.f); t1[s] = l1; ag[s] = cb+1; }
                    else su[s] += fexp(l1 - t1[s]);
                }
        }
    }
    float* smax = (float*)sm; float* ssum = smax + 2048; int* sarg = (int*)(ssum + 2048);
    int sc = wn*4 + tig;
#pragma unroll
    for (int mi = 0; mi < 4; mi++)
#pragma unroll
        for (int h = 0; h < 2; h++){
            int row = wm*64 + mi*16 + gid + h*8, s = mi*2 + h;
            smax[row*16 + sc] = t1[s]; ssum[row*16 + sc] = su[s]; sarg[row*16 + sc] = ag[s];
        }
    __syncthreads();
    if (tid < 128){
        int row = tid; float bm = -1e30f; int ba = 1 << 30;
#pragma unroll
        for (int i = 0; i < 16; i++){
            float m = smax[row*16 + i]; int a = sarg[row*16 + i];
            if (m > bm || (m == bm && a < ba)){ bm = m; ba = a; }
        }
        float ssv = 0.f;
#pragma unroll
        for (int i = 0; i < 16; i++) ssv = fmaf(ssum[row*16 + i], __expf(smax[row*16 + i] - bm), ssv);
        g_arg[m0 + row] = ba; g_sum[m0 + row] = ssv;
    }
}

// ============ finalize ============
__global__ void finalize_kernel(float* __restrict__ out){
    int r = blockIdx.x*256 + threadIdx.x;
    if (r >= BRN) return;
    float m0 = 1.f / g_sum[r], m1 = 1.f / g_sum[BRN + r];
    int i0 = g_arg[r], i1 = g_arg[BRN + r];
    bool c0 = (i0 != 0) && (m0 >= 0.1f);
    bool c1 = c0 && (i1 != 0) && (m1 >= 0.1f);
    out[r] = c0 ? (c1 ? m0*m1 : m0) : 0.f;
    out[BRN + r] = (float)i0; out[2*BRN + r] = (float)i1;
    out[3*BRN + r] = (float)((int)c0 + (int)c1);
}

extern "C" void kernel_launch(void* const* d_in, const int* in_sizes, int n_in,
                              void* d_out, int out_size){
    const float* x    = (const float*)d_in[0];
    const float* na   = (const float*)d_in[1];
    const float* v_w  = (const float*)d_in[2];
    const float* v_b  = (const float*)d_in[3];
    const float* o_w  = (const float*)d_in[4];
    const float* o_b  = (const float*)d_in[5];
    const float* ln_g = (const float*)d_in[6];
    const float* ln_b = (const float*)d_in[7];
    const float* w1   = (const float*)d_in[8];
    const float* b1   = (const float*)d_in[9];
    const float* w2   = (const float*)d_in[10];
    const float* b2   = (const float*)d_in[11];
    float* out = (float*)d_out;

    float* wc; cudaGetSymbolAddress((void**)&wc, g_Wc);
    uint8_t *wcimg, *w1img, *w2img;
    cudaGetSymbolAddress((void**)&wcimg, g_wcimg);
    cudaGetSymbolAddress((void**)&w1img, g_w1img);
    cudaGetSymbolAddress((void**)&w2img, g_w2img);

    combine_w_kernel<<<DN, 256>>>(o_w, v_w, v_b, o_b);
    wsplit_kernel<<<(DN*DN/2)/256, 256>>>(wc, wcimg, DN, 8);
    wsplit_kernel<<<(HN*DN/2)/256, 256>>>(w1, w1img, DN, 8);
    wsplit_kernel<<<((size_t)NRELN*HN/2)/256, 256>>>(w2, w2img, HN, 9);
    xsplit_kernel<<<(BRN*DN/8)/256, 256>>>(x);
    attn_tc<<<dim3(DN/128, BRN/128), 256>>>();
    ln_split_kernel<<<ROWS2, 128>>>(x, na, ln_g, ln_b);
    gemm_g_tc<<<dim3(HN/128, ROWS2/128), 256>>>(b1);
    logits_tc<<<ROWS2/128, 256>>>(b2);
    finalize_kernel<<<BRN/256, 256>>>(out);
}